// round 13
// baseline (speedup 1.0000x reference)
#include <cuda_runtime.h>
#include <cuda_fp16.h>
#include <math_constants.h>
#include <cstdint>

// Problem constants
#define TT 2048
#define CC 1024
#define HH 16
#define DH 64
#define BB 2

#define SW(off) ((uint32_t)(off) ^ ((((uint32_t)(off)) >> 3) & 0x70u))

// ---------------------------------------------------------------------------
// PTX helpers (base-target safe)
// ---------------------------------------------------------------------------
__device__ __forceinline__ uint32_t smem_u32(const void* p) {
    uint32_t a;
    asm("{ .reg .u64 t; cvta.to.shared.u64 t, %1; cvt.u32.u64 %0, t; }"
        : "=r"(a) : "l"(p));
    return a;
}
__device__ __forceinline__ void ldsm_x4(uint32_t addr, uint32_t &r0, uint32_t &r1,
                                        uint32_t &r2, uint32_t &r3) {
    asm volatile("ldmatrix.sync.aligned.m8n8.x4.shared.b16 {%0,%1,%2,%3}, [%4];"
                 : "=r"(r0), "=r"(r1), "=r"(r2), "=r"(r3) : "r"(addr));
}
__device__ __forceinline__ void ldsm_x4t(uint32_t addr, uint32_t &r0, uint32_t &r1,
                                         uint32_t &r2, uint32_t &r3) {
    asm volatile("ldmatrix.sync.aligned.m8n8.x4.trans.shared.b16 {%0,%1,%2,%3}, [%4];"
                 : "=r"(r0), "=r"(r1), "=r"(r2), "=r"(r3) : "r"(addr));
}
__device__ __forceinline__ void mma_f16(float* c, uint32_t a0, uint32_t a1,
                                        uint32_t a2, uint32_t a3,
                                        uint32_t b0, uint32_t b1) {
    asm volatile("mma.sync.aligned.m16n8k16.row.col.f32.f16.f16.f32 "
                 "{%0,%1,%2,%3}, {%4,%5,%6,%7}, {%8,%9}, {%0,%1,%2,%3};"
                 : "+f"(c[0]), "+f"(c[1]), "+f"(c[2]), "+f"(c[3])
                 : "r"(a0), "r"(a1), "r"(a2), "r"(a3), "r"(b0), "r"(b1));
}
__device__ __forceinline__ void cp_async16(uint32_t dst, const void* src) {
    asm volatile("cp.async.cg.shared.global [%0], [%1], 16;"
                 :: "r"(dst), "l"(src) : "memory");
}
#define CP_COMMIT() asm volatile("cp.async.commit_group;" ::: "memory")
#define CP_WAIT0()  asm volatile("cp.async.wait_group 0;" ::: "memory")
#define CP_WAIT1()  asm volatile("cp.async.wait_group 1;" ::: "memory")

__device__ __forceinline__ uint32_t pack_f16x2(float lo, float hi) {
    uint32_t d;
    asm("cvt.rn.f16x2.f32 %0, %1, %2;" : "=r"(d) : "f"(hi), "f"(lo));
    return d;
}
__device__ __forceinline__ uint32_t ex2_f16x2(uint32_t a) {
    uint32_t d;
    asm("ex2.approx.f16x2 %0, %1;" : "=r"(d) : "r"(a));
    return d;
}

// ---------------------------------------------------------------------------
// Scratch
// ---------------------------------------------------------------------------
__device__ __half g_xh[(size_t)BB * TT * CC];
__device__ __half g_qkvh[(size_t)BB * TT * 3 * CC];
__device__ __half g_yh[(size_t)BB * TT * CC];
__device__ __half g_wah[(size_t)3 * CC * CC];          // W_attn^T [3C, C] fp16
__device__ __half g_wph[(size_t)CC * CC];              // W_proj^T [C, C]  fp16

// ---------------------------------------------------------------------------
// fp32 -> fp16 convert
// ---------------------------------------------------------------------------
__global__ __launch_bounds__(256) void cvt_half(
    const float* __restrict__ in, __half* __restrict__ h, int n2)
{
    int i = blockIdx.x * 256 + threadIdx.x;
    if (i >= n2) return;
    float2 v = ((const float2*)in)[i];
    ((half2*)h)[i] = __floats2half2_rn(v.x, v.y);
}

// ---------------------------------------------------------------------------
// Both weights: fp32 [K,N] -> fp16 transposed [N,K], single launch.
// ---------------------------------------------------------------------------
__global__ __launch_bounds__(256) void cvt_t2(
    const float* __restrict__ Wa, __half* __restrict__ wah,
    const float* __restrict__ Wp, __half* __restrict__ wph)
{
    __shared__ float ts[32][33];
    int tx = threadIdx.x, ty = threadIdx.y;
    int bx = blockIdx.x, by = blockIdx.y;
    const float* in;
    __half* out;
    int N;
    if (bx < 96) { in = Wa; out = wah; N = 3 * CC; }
    else         { in = Wp; out = wph; N = CC; bx -= 96; }
    const int K = CC;
    #pragma unroll
    for (int j = 0; j < 4; j++) {
        int k = by * 32 + ty + j * 8;
        ts[ty + j * 8][tx] = in[(size_t)k * N + bx * 32 + tx];
    }
    __syncthreads();
    #pragma unroll
    for (int j = 0; j < 4; j++) {
        int nrow = bx * 32 + ty + j * 8;
        out[(size_t)nrow * K + by * 32 + tx] = __float2half(ts[tx][ty + j * 8]);
    }
}

// ---------------------------------------------------------------------------
// Tensor-core GEMM, fp16: C = Ah @ Bh^T + bias
// CTA 128x256, 8 warps of 64x64, k128 chunks, 2-stage cp.async, 1 CTA/SM.
// ---------------------------------------------------------------------------
#define STG_BYTES 98304
#define GSMEM (2 * STG_BYTES + 1024)

template<bool HALF_OUT>
__global__ __launch_bounds__(256, 1) void gemm_mma(
    const __half* __restrict__ Ah, const __half* __restrict__ Bh,
    const float* __restrict__ bias, float* __restrict__ Cf,
    __half* __restrict__ Ch, int Ncols, int K)
{
    extern __shared__ char dsm[];
    const uint32_t sb = (smem_u32(dsm) + 1023u) & ~1023u;

    const int tid = threadIdx.x;
    const int lid = tid & 31;
    const int wid = tid >> 5;
    const int wm = (wid >> 2) * 64;
    const int wn = (wid & 3) * 64;
    const int bm = blockIdx.y * 128;
    const int bn = blockIdx.x * 256;

    float c[4][8][4];
    #pragma unroll
    for (int mt = 0; mt < 4; mt++)
        #pragma unroll
        for (int nt = 0; nt < 8; nt++)
            #pragma unroll
            for (int e = 0; e < 4; e++) c[mt][nt][e] = 0.f;

    auto load_chunk = [&](int ch, int stg) {
        const int k0 = ch << 7;
        const uint32_t base = sb + (uint32_t)(stg * STG_BYTES);
        #pragma unroll
        for (int j = 0; j < 8; j++) {          // A
            int idx = tid + j * 256;
            int row = idx >> 4;
            int c16f = idx & 15;
            int sub = c16f >> 3, c16 = c16f & 7;
            cp_async16(base + (uint32_t)(sub << 14) + SW(row * 128 + c16 * 16),
                       Ah + (size_t)(bm + row) * K + k0 + sub * 64 + c16 * 8);
        }
        #pragma unroll
        for (int j = 0; j < 16; j++) {         // B
            int idx = tid + j * 256;
            int row = idx >> 4;
            int c16f = idx & 15;
            int sub = c16f >> 3, c16 = c16f & 7;
            cp_async16(base + 32768u + (uint32_t)(sub << 15) + SW(row * 128 + c16 * 16),
                       Bh + (size_t)(bn + row) * K + k0 + sub * 64 + c16 * 8);
        }
    };

    auto compute = [&](int stg) {
        const uint32_t tb = sb + (uint32_t)(stg * STG_BYTES);
        #pragma unroll
        for (int ks = 0; ks < 8; ks++) {
            const int sub = ks >> 2, ksl = ks & 3;
            const uint32_t abase = tb + (uint32_t)(sub << 14);
            const uint32_t bbase = tb + 32768u + (uint32_t)(sub << 15);
            uint32_t ah[4][4];
            #pragma unroll
            for (int mt = 0; mt < 4; mt++) {
                int row = wm + mt * 16 + (lid & 15);
                ldsm_x4(abase + SW(row * 128 + ksl * 32 + ((lid >> 4) << 4)),
                        ah[mt][0], ah[mt][1], ah[mt][2], ah[mt][3]);
            }
            #pragma unroll
            for (int ntp = 0; ntp < 4; ntp++) {
                int rowb = wn + ntp * 16 + ((lid >> 4) << 3) + (lid & 7);
                uint32_t offb = SW(rowb * 128 + ksl * 32 + (((lid >> 3) & 1) << 4));
                uint32_t bh[4];
                ldsm_x4(bbase + offb, bh[0], bh[1], bh[2], bh[3]);
                #pragma unroll
                for (int half = 0; half < 2; half++) {
                    int nt = ntp * 2 + half;
                    #pragma unroll
                    for (int mt = 0; mt < 4; mt++)
                        mma_f16(c[mt][nt], ah[mt][0], ah[mt][1], ah[mt][2], ah[mt][3],
                                bh[half * 2], bh[half * 2 + 1]);
                }
            }
        }
    };

    const int nch = K >> 7;                 // 8 chunks for K=1024
    load_chunk(0, 0); CP_COMMIT();

    for (int ch = 0; ch < nch; ch++) {
        CP_WAIT0();
        __syncthreads();
        if (ch + 1 < nch) { load_chunk(ch + 1, (ch + 1) & 1); CP_COMMIT(); }
        compute(ch & 1);
    }

    #pragma unroll
    for (int mt = 0; mt < 4; mt++) {
        #pragma unroll
        for (int nt = 0; nt < 8; nt++) {
            int m0 = bm + wm + mt * 16 + (lid >> 2);
            int n  = bn + wn + nt * 8 + ((lid & 3) << 1);
            float b0 = bias[n], b1 = bias[n + 1];
            float v00 = c[mt][nt][0] + b0, v01 = c[mt][nt][1] + b1;
            float v10 = c[mt][nt][2] + b0, v11 = c[mt][nt][3] + b1;
            if (HALF_OUT) {
                *(half2*)(Ch + (size_t)m0 * Ncols + n) =
                    __floats2half2_rn(v00, v01);
                *(half2*)(Ch + (size_t)(m0 + 8) * Ncols + n) =
                    __floats2half2_rn(v10, v11);
            } else {
                float2 p0 = {v00, v01}, p1 = {v10, v11};
                *(float2*)(Cf + (size_t)m0 * Ncols + n) = p0;
                *(float2*)(Cf + (size_t)(m0 + 8) * Ncols + n) = p1;
            }
        }
    }
}

// ---------------------------------------------------------------------------
// Flash attention (causal), fp16: S = Qh Kh^T; O += P Vh.
// Block = (b, h, q-tile 128). 8 warps of 16 q-rows (256 thr), 2 CTAs/SM
// -> 4 warps/SMSP for latency hiding. 3-stage KV pipeline (Kh 0 | Vh 8K).
// Softmax: P = ex2.approx.f16x2(pack(s*SCL - mn)); row-sums via ones-mma.
// ---------------------------------------------------------------------------
#define KVBUF 16384
#define ATT_SMEM (1024 + 3 * KVBUF)
#define ONES_F16X2 0x3C003C00u

__global__ __launch_bounds__(256, 2) void attn_mma(
    const __half* __restrict__ qkvh, __half* __restrict__ yh)
{
    extern __shared__ char asm_[];
    const uint32_t sb = (smem_u32(asm_) + 1023u) & ~1023u;

    const int tid = threadIdx.x;
    const int lid = tid & 31;
    const int w = tid >> 5;                       // 0..7
    const int qt = gridDim.x - 1 - blockIdx.x;    // longest first
    const int h = blockIdx.y;
    const int b = blockIdx.z;
    const size_t bT = (size_t)b * TT;
    const int RS = 3 * CC;
    const float SCL = 0.18033688f;                // 0.125 * log2(e)

    // ---- stage Q (128 x 64 fp16 = 16KB) into buffer0, extract fragments
    {
        const __half* qg = qkvh + (bT + qt * 128) * RS + h * DH;
        #pragma unroll
        for (int j = 0; j < 4; j++) {
            int idx = tid + j * 256;              // 0..1023
            int row = idx >> 3, c16 = idx & 7;
            cp_async16(sb + SW(row * 128 + c16 * 16),
                       qg + (size_t)row * RS + c16 * 8);
        }
    }
    CP_COMMIT(); CP_WAIT0();
    __syncthreads();
    uint32_t qh[4][4];
    #pragma unroll
    for (int ks = 0; ks < 4; ks++) {
        int row = w * 16 + (lid & 15);
        ldsm_x4(sb + SW(row * 128 + ks * 32 + ((lid >> 4) << 4)),
                qh[ks][0], qh[ks][1], qh[ks][2], qh[ks][3]);
    }
    __syncthreads();

    auto load_kv = [&](int kt, int buf) {
        const __half* kh_g = qkvh + (bT + kt * 64) * RS + CC + h * DH;
        const __half* vh_g = kh_g + CC;
        const uint32_t base = sb + (uint32_t)(buf * KVBUF);
        #pragma unroll
        for (int j = 0; j < 4; j++) {
            int idx = tid + j * 256;              // 0..1023
            int half = idx >> 9;
            int r = idx & 511;
            int row = r >> 3, c16 = r & 7;
            uint32_t sw = SW(row * 128 + c16 * 16);
            const __half* src = (half ? vh_g : kh_g) + (size_t)row * RS + c16 * 8;
            cp_async16(base + (uint32_t)(half << 13) + sw, src);
        }
    };

    float o[8][4];
    #pragma unroll
    for (int nt = 0; nt < 8; nt++)
        #pragma unroll
        for (int e = 0; e < 4; e++) o[nt][e] = 0.f;
    float m0 = -CUDART_INF_F, m1 = -CUDART_INF_F, l0 = 0.f, l1 = 0.f;
    const int gr0 = qt * 128 + w * 16;            // warp's first global q row
    const int r0 = (lid >> 2);
    const int cbase = (lid & 3) << 1;

    const int kt_max = 2 * qt + 1;
    load_kv(0, 0); CP_COMMIT();
    if (kt_max >= 1) { load_kv(1, 1); CP_COMMIT(); }

    for (int kt = 0; kt <= kt_max; kt++) {
        const int buf = kt % 3;
        const uint32_t tb = sb + (uint32_t)(buf * KVBUF);
        if (kt + 1 <= kt_max) CP_WAIT1(); else CP_WAIT0();
        __syncthreads();
        if (kt + 2 <= kt_max) { load_kv(kt + 2, (kt + 2) % 3); CP_COMMIT(); }

        if (kt * 64 <= gr0 + 15) {                // tile not fully masked
            // S_raw = Qh Kh^T  (16 x 64 per warp)
            float s[8][4];
            #pragma unroll
            for (int nt = 0; nt < 8; nt++)
                #pragma unroll
                for (int e = 0; e < 4; e++) s[nt][e] = 0.f;

            #pragma unroll
            for (int ks = 0; ks < 4; ks++) {
                #pragma unroll
                for (int ntp = 0; ntp < 4; ntp++) {
                    int rowb = ntp * 16 + ((lid >> 4) << 3) + (lid & 7);
                    uint32_t offb = SW(rowb * 128 + ks * 32 + (((lid >> 3) & 1) << 4));
                    uint32_t kh[4];
                    ldsm_x4(tb + offb, kh[0], kh[1], kh[2], kh[3]);
                    mma_f16(s[ntp * 2],     qh[ks][0], qh[ks][1], qh[ks][2], qh[ks][3],
                            kh[0], kh[1]);
                    mma_f16(s[ntp * 2 + 1], qh[ks][0], qh[ks][1], qh[ks][2], qh[ks][3],
                            kh[2], kh[3]);
                }
            }

            // causal mask on raw scores (diagonal-overlapping tiles only)
            if (kt * 64 + 63 > gr0) {
                int gr = gr0 + r0;
                #pragma unroll
                for (int nt = 0; nt < 8; nt++) {
                    int gc = kt * 64 + nt * 8 + cbase;
                    if (gc     > gr)     s[nt][0] = -CUDART_INF_F;
                    if (gc + 1 > gr)     s[nt][1] = -CUDART_INF_F;
                    if (gc     > gr + 8) s[nt][2] = -CUDART_INF_F;
                    if (gc + 1 > gr + 8) s[nt][3] = -CUDART_INF_F;
                }
            }

            // row max (raw), running max (log2 domain), alpha, o-rescale
            float mx0 = -CUDART_INF_F, mx1 = -CUDART_INF_F;
            #pragma unroll
            for (int nt = 0; nt < 8; nt++) {
                mx0 = fmaxf(mx0, fmaxf(s[nt][0], s[nt][1]));
                mx1 = fmaxf(mx1, fmaxf(s[nt][2], s[nt][3]));
            }
            mx0 = fmaxf(mx0, __shfl_xor_sync(0xffffffffu, mx0, 1));
            mx0 = fmaxf(mx0, __shfl_xor_sync(0xffffffffu, mx0, 2));
            mx1 = fmaxf(mx1, __shfl_xor_sync(0xffffffffu, mx1, 1));
            mx1 = fmaxf(mx1, __shfl_xor_sync(0xffffffffu, mx1, 2));
            float mn0 = fmaxf(m0, mx0 * SCL), mn1 = fmaxf(m1, mx1 * SCL);
            float a0 = exp2f(m0 - mn0), a1 = exp2f(m1 - mn1);
            m0 = mn0;  m1 = mn1;
            #pragma unroll
            for (int nt = 0; nt < 8; nt++) {
                o[nt][0] *= a0; o[nt][1] *= a0;
                o[nt][2] *= a1; o[nt][3] *= a1;
            }

            // PV with inline P = ex2(pack(s*SCL - mn)); row sums via ones-mma
            float ssum[4] = {0.f, 0.f, 0.f, 0.f};
            #pragma unroll
            for (int ks = 0; ks < 4; ks++) {
                const int t0 = ks * 2, t1 = ks * 2 + 1;
                uint32_t ph0 = ex2_f16x2(pack_f16x2(
                    fmaf(s[t0][0], SCL, -mn0), fmaf(s[t0][1], SCL, -mn0)));
                uint32_t ph1 = ex2_f16x2(pack_f16x2(
                    fmaf(s[t0][2], SCL, -mn1), fmaf(s[t0][3], SCL, -mn1)));
                uint32_t ph2 = ex2_f16x2(pack_f16x2(
                    fmaf(s[t1][0], SCL, -mn0), fmaf(s[t1][1], SCL, -mn0)));
                uint32_t ph3 = ex2_f16x2(pack_f16x2(
                    fmaf(s[t1][2], SCL, -mn1), fmaf(s[t1][3], SCL, -mn1)));
                mma_f16(ssum, ph0, ph1, ph2, ph3, ONES_F16X2, ONES_F16X2);
                int rowv = ks * 16 + (lid & 15);
                #pragma unroll
                for (int nt2 = 0; nt2 < 4; nt2++) {
                    uint32_t offv = SW(rowv * 128 + nt2 * 32 + ((lid >> 4) << 4));
                    uint32_t vh[4];
                    ldsm_x4t(tb + 8192 + offv, vh[0], vh[1], vh[2], vh[3]);
                    mma_f16(o[nt2 * 2],     ph0, ph1, ph2, ph3, vh[0], vh[1]);
                    mma_f16(o[nt2 * 2 + 1], ph0, ph1, ph2, ph3, vh[2], vh[3]);
                }
            }

            l0 = l0 * a0 + ssum[0];
            l1 = l1 * a1 + ssum[2];
        }
        __syncthreads();
    }

    // Epilogue: normalize, fp16 out
    float i0 = 1.f / l0, i1 = 1.f / l1;
    size_t row0 = (bT + (size_t)(qt * 128 + w * 16 + r0)) * CC + h * DH;
    size_t row1 = row0 + (size_t)8 * CC;
    #pragma unroll
    for (int nt = 0; nt < 8; nt++) {
        int n = nt * 8 + cbase;
        *(half2*)(yh + row0 + n) =
            __floats2half2_rn(o[nt][0] * i0, o[nt][1] * i0);
        *(half2*)(yh + row1 + n) =
            __floats2half2_rn(o[nt][2] * i1, o[nt][3] * i1);
    }
}

// ---------------------------------------------------------------------------
extern "C" void kernel_launch(void* const* d_in, const int* in_sizes, int n_in,
                              void* d_out, int out_size)
{
    const float* x      = (const float*)d_in[0];
    const float* W_attn = (const float*)d_in[1];
    const float* b_attn = (const float*)d_in[2];
    const float* W_proj = (const float*)d_in[3];
    const float* b_proj = (const float*)d_in[4];
    float* out = (float*)d_out;

    __half *xh, *qkvh, *yh, *wah, *wph;
    cudaGetSymbolAddress((void**)&xh, g_xh);
    cudaGetSymbolAddress((void**)&qkvh, g_qkvh);
    cudaGetSymbolAddress((void**)&yh, g_yh);
    cudaGetSymbolAddress((void**)&wah, g_wah);
    cudaGetSymbolAddress((void**)&wph, g_wph);

    const int M = BB * TT;       // 4096
    const int N1 = 3 * CC;       // 3072
    const int N2 = CC;           // 1024
    const int K = CC;            // 1024

    cudaFuncSetAttribute(gemm_mma<true>,
                         cudaFuncAttributeMaxDynamicSharedMemorySize, GSMEM);
    cudaFuncSetAttribute(gemm_mma<false>,
                         cudaFuncAttributeMaxDynamicSharedMemorySize, GSMEM);
    cudaFuncSetAttribute(attn_mma,
                         cudaFuncAttributeMaxDynamicSharedMemorySize, ATT_SMEM);

    // Prep: x -> fp16; both weights -> transposed fp16 (single launch)
    cvt_half<<<(M * K / 2 + 255) / 256, 256>>>(x, xh, M * K / 2);
    {
        dim3 grid(96 + 32, 32), blk(32, 8);
        cvt_t2<<<grid, blk>>>(W_attn, wah, W_proj, wph);
    }

    // 1) qkv = x @ W_attn + b_attn  (fp16)
    {
        dim3 grid(N1 / 256, M / 128);
        gemm_mma<true><<<grid, 256, GSMEM>>>(xh, wah, b_attn,
                                             nullptr, qkvh, N1, K);
    }

    // 2) Flash attention -> y (fp16)
    {
        dim3 grid(TT / 128, HH, BB);
        attn_mma<<<grid, 256, ATT_SMEM>>>(qkvh, yh);
    }

    // 3) out = y @ W_proj + b_proj (fp32)
    {
        dim3 grid(N2 / 256, M / 128);
        gemm_mma<false><<<grid, 256, GSMEM>>>(yh, wph, b_proj,
                                              out, nullptr, N2, K);
    }
}

// round 14
// speedup vs baseline: 1.0634x; 1.0634x over previous
#include <cuda_runtime.h>
#include <cuda_fp16.h>
#include <math_constants.h>
#include <cstdint>

// Problem constants
#define TT 2048
#define CC 1024
#define HH 16
#define DH 64
#define BB 2

#define SW(off) ((uint32_t)(off) ^ ((((uint32_t)(off)) >> 3) & 0x70u))

// ---------------------------------------------------------------------------
// PTX helpers (base-target safe)
// ---------------------------------------------------------------------------
__device__ __forceinline__ uint32_t smem_u32(const void* p) {
    uint32_t a;
    asm("{ .reg .u64 t; cvta.to.shared.u64 t, %1; cvt.u32.u64 %0, t; }"
        : "=r"(a) : "l"(p));
    return a;
}
__device__ __forceinline__ void ldsm_x4(uint32_t addr, uint32_t &r0, uint32_t &r1,
                                        uint32_t &r2, uint32_t &r3) {
    asm volatile("ldmatrix.sync.aligned.m8n8.x4.shared.b16 {%0,%1,%2,%3}, [%4];"
                 : "=r"(r0), "=r"(r1), "=r"(r2), "=r"(r3) : "r"(addr));
}
__device__ __forceinline__ void ldsm_x4t(uint32_t addr, uint32_t &r0, uint32_t &r1,
                                         uint32_t &r2, uint32_t &r3) {
    asm volatile("ldmatrix.sync.aligned.m8n8.x4.trans.shared.b16 {%0,%1,%2,%3}, [%4];"
                 : "=r"(r0), "=r"(r1), "=r"(r2), "=r"(r3) : "r"(addr));
}
__device__ __forceinline__ void mma_f16(float* c, uint32_t a0, uint32_t a1,
                                        uint32_t a2, uint32_t a3,
                                        uint32_t b0, uint32_t b1) {
    asm volatile("mma.sync.aligned.m16n8k16.row.col.f32.f16.f16.f32 "
                 "{%0,%1,%2,%3}, {%4,%5,%6,%7}, {%8,%9}, {%0,%1,%2,%3};"
                 : "+f"(c[0]), "+f"(c[1]), "+f"(c[2]), "+f"(c[3])
                 : "r"(a0), "r"(a1), "r"(a2), "r"(a3), "r"(b0), "r"(b1));
}
__device__ __forceinline__ void cp_async16(uint32_t dst, const void* src) {
    asm volatile("cp.async.cg.shared.global [%0], [%1], 16;"
                 :: "r"(dst), "l"(src) : "memory");
}
#define CP_COMMIT() asm volatile("cp.async.commit_group;" ::: "memory")
#define CP_WAIT0()  asm volatile("cp.async.wait_group 0;" ::: "memory")
#define CP_WAIT1()  asm volatile("cp.async.wait_group 1;" ::: "memory")

__device__ __forceinline__ uint32_t pack_f16x2(float lo, float hi) {
    uint32_t d;
    asm("cvt.rn.f16x2.f32 %0, %1, %2;" : "=r"(d) : "f"(hi), "f"(lo));
    return d;
}
__device__ __forceinline__ uint32_t ex2_f16x2(uint32_t a) {
    uint32_t d;
    asm("ex2.approx.f16x2 %0, %1;" : "=r"(d) : "r"(a));
    return d;
}

// ---------------------------------------------------------------------------
// Scratch
// ---------------------------------------------------------------------------
__device__ __half g_xh[(size_t)BB * TT * CC];
__device__ __half g_qkvh[(size_t)BB * TT * 3 * CC];
__device__ __half g_yh[(size_t)BB * TT * CC];
__device__ __half g_wah[(size_t)3 * CC * CC];          // W_attn^T [3C, C] fp16
__device__ __half g_wph[(size_t)CC * CC];              // W_proj^T [C, C]  fp16

// ---------------------------------------------------------------------------
// fp32 -> fp16 convert
// ---------------------------------------------------------------------------
__global__ __launch_bounds__(256) void cvt_half(
    const float* __restrict__ in, __half* __restrict__ h, int n2)
{
    int i = blockIdx.x * 256 + threadIdx.x;
    if (i >= n2) return;
    float2 v = ((const float2*)in)[i];
    ((half2*)h)[i] = __floats2half2_rn(v.x, v.y);
}

// ---------------------------------------------------------------------------
// Both weights: fp32 [K,N] -> fp16 transposed [N,K], single launch.
// ---------------------------------------------------------------------------
__global__ __launch_bounds__(256) void cvt_t2(
    const float* __restrict__ Wa, __half* __restrict__ wah,
    const float* __restrict__ Wp, __half* __restrict__ wph)
{
    __shared__ float ts[32][33];
    int tx = threadIdx.x, ty = threadIdx.y;
    int bx = blockIdx.x, by = blockIdx.y;
    const float* in;
    __half* out;
    int N;
    if (bx < 96) { in = Wa; out = wah; N = 3 * CC; }
    else         { in = Wp; out = wph; N = CC; bx -= 96; }
    const int K = CC;
    #pragma unroll
    for (int j = 0; j < 4; j++) {
        int k = by * 32 + ty + j * 8;
        ts[ty + j * 8][tx] = in[(size_t)k * N + bx * 32 + tx];
    }
    __syncthreads();
    #pragma unroll
    for (int j = 0; j < 4; j++) {
        int nrow = bx * 32 + ty + j * 8;
        out[(size_t)nrow * K + by * 32 + tx] = __float2half(ts[tx][ty + j * 8]);
    }
}

// ---------------------------------------------------------------------------
// Tensor-core GEMM, fp16: C = Ah @ Bh^T + bias
// CTA 128x256, 8 warps of 64x64, k128 chunks, 2-stage cp.async, 1 CTA/SM.
// Bias staged in smem (tail region) to avoid scattered epilogue LDG.
// ---------------------------------------------------------------------------
#define STG_BYTES 98304
#define GSMEM (2 * STG_BYTES + 2048)

template<bool HALF_OUT>
__global__ __launch_bounds__(256, 1) void gemm_mma(
    const __half* __restrict__ Ah, const __half* __restrict__ Bh,
    const float* __restrict__ bias, float* __restrict__ Cf,
    __half* __restrict__ Ch, int Ncols, int K)
{
    extern __shared__ char dsm[];
    const uint32_t sb = (smem_u32(dsm) + 1023u) & ~1023u;
    float* bias_s = (float*)(dsm + ((sb - smem_u32(dsm)) + 2 * STG_BYTES));

    const int tid = threadIdx.x;
    const int lid = tid & 31;
    const int wid = tid >> 5;
    const int wm = (wid >> 2) * 64;
    const int wn = (wid & 3) * 64;
    const int bm = blockIdx.y * 128;
    const int bn = blockIdx.x * 256;

    bias_s[tid] = bias[bn + tid];   // 256 floats, one per thread

    float c[4][8][4];
    #pragma unroll
    for (int mt = 0; mt < 4; mt++)
        #pragma unroll
        for (int nt = 0; nt < 8; nt++)
            #pragma unroll
            for (int e = 0; e < 4; e++) c[mt][nt][e] = 0.f;

    auto load_chunk = [&](int ch, int stg) {
        const int k0 = ch << 7;
        const uint32_t base = sb + (uint32_t)(stg * STG_BYTES);
        #pragma unroll
        for (int j = 0; j < 8; j++) {          // A
            int idx = tid + j * 256;
            int row = idx >> 4;
            int c16f = idx & 15;
            int sub = c16f >> 3, c16 = c16f & 7;
            cp_async16(base + (uint32_t)(sub << 14) + SW(row * 128 + c16 * 16),
                       Ah + (size_t)(bm + row) * K + k0 + sub * 64 + c16 * 8);
        }
        #pragma unroll
        for (int j = 0; j < 16; j++) {         // B
            int idx = tid + j * 256;
            int row = idx >> 4;
            int c16f = idx & 15;
            int sub = c16f >> 3, c16 = c16f & 7;
            cp_async16(base + 32768u + (uint32_t)(sub << 15) + SW(row * 128 + c16 * 16),
                       Bh + (size_t)(bn + row) * K + k0 + sub * 64 + c16 * 8);
        }
    };

    auto compute = [&](int stg) {
        const uint32_t tb = sb + (uint32_t)(stg * STG_BYTES);
        #pragma unroll
        for (int ks = 0; ks < 8; ks++) {
            const int sub = ks >> 2, ksl = ks & 3;
            const uint32_t abase = tb + (uint32_t)(sub << 14);
            const uint32_t bbase = tb + 32768u + (uint32_t)(sub << 15);
            uint32_t ah[4][4];
            #pragma unroll
            for (int mt = 0; mt < 4; mt++) {
                int row = wm + mt * 16 + (lid & 15);
                ldsm_x4(abase + SW(row * 128 + ksl * 32 + ((lid >> 4) << 4)),
                        ah[mt][0], ah[mt][1], ah[mt][2], ah[mt][3]);
            }
            #pragma unroll
            for (int ntp = 0; ntp < 4; ntp++) {
                int rowb = wn + ntp * 16 + ((lid >> 4) << 3) + (lid & 7);
                uint32_t offb = SW(rowb * 128 + ksl * 32 + (((lid >> 3) & 1) << 4));
                uint32_t bh[4];
                ldsm_x4(bbase + offb, bh[0], bh[1], bh[2], bh[3]);
                #pragma unroll
                for (int half = 0; half < 2; half++) {
                    int nt = ntp * 2 + half;
                    #pragma unroll
                    for (int mt = 0; mt < 4; mt++)
                        mma_f16(c[mt][nt], ah[mt][0], ah[mt][1], ah[mt][2], ah[mt][3],
                                bh[half * 2], bh[half * 2 + 1]);
                }
            }
        }
    };

    const int nch = K >> 7;                 // 8 chunks for K=1024
    load_chunk(0, 0); CP_COMMIT();

    for (int ch = 0; ch < nch; ch++) {
        CP_WAIT0();
        __syncthreads();
        if (ch + 1 < nch) { load_chunk(ch + 1, (ch + 1) & 1); CP_COMMIT(); }
        compute(ch & 1);
    }

    #pragma unroll
    for (int mt = 0; mt < 4; mt++) {
        #pragma unroll
        for (int nt = 0; nt < 8; nt++) {
            int m0 = bm + wm + mt * 16 + (lid >> 2);
            int nl = wn + nt * 8 + ((lid & 3) << 1);   // local col in [0,256)
            int n  = bn + nl;
            float b0 = bias_s[nl], b1 = bias_s[nl + 1];
            float v00 = c[mt][nt][0] + b0, v01 = c[mt][nt][1] + b1;
            float v10 = c[mt][nt][2] + b0, v11 = c[mt][nt][3] + b1;
            if (HALF_OUT) {
                *(half2*)(Ch + (size_t)m0 * Ncols + n) =
                    __floats2half2_rn(v00, v01);
                *(half2*)(Ch + (size_t)(m0 + 8) * Ncols + n) =
                    __floats2half2_rn(v10, v11);
            } else {
                float2 p0 = {v00, v01}, p1 = {v10, v11};
                *(float2*)(Cf + (size_t)m0 * Ncols + n) = p0;
                *(float2*)(Cf + (size_t)(m0 + 8) * Ncols + n) = p1;
            }
        }
    }
}

// ---------------------------------------------------------------------------
// Flash attention (causal), fp16: S = Qh Kh^T; O += P Vh.
// Block = (b, h, q-tile 128). 4 warps of 32 q-rows, 2 CTAs/SM.
// 3-stage KV pipeline (16KB each: Kh 0 | Vh 8K).
// Softmax: P = ex2.approx.f16x2(pack(s*SCL - mn)); row-sums via ones-mma.
// (R12 configuration — measured optimum.)
// ---------------------------------------------------------------------------
#define KVBUF 16384
#define ATT_SMEM (1024 + 3 * KVBUF)
#define ONES_F16X2 0x3C003C00u

__global__ __launch_bounds__(128, 2) void attn_mma(
    const __half* __restrict__ qkvh, __half* __restrict__ yh)
{
    extern __shared__ char asm_[];
    const uint32_t sb = (smem_u32(asm_) + 1023u) & ~1023u;

    const int tid = threadIdx.x;
    const int lid = tid & 31;
    const int w = tid >> 5;
    const int qt = gridDim.x - 1 - blockIdx.x;    // longest first
    const int h = blockIdx.y;
    const int b = blockIdx.z;
    const size_t bT = (size_t)b * TT;
    const int RS = 3 * CC;
    const float SCL = 0.18033688f;                // 0.125 * log2(e)

    // ---- stage Q (128 x 64 fp16 = 16KB) into buffer0, extract fragments
    {
        const __half* qg = qkvh + (bT + qt * 128) * RS + h * DH;
        #pragma unroll
        for (int j = 0; j < 8; j++) {
            int idx = tid + j * 128;
            int row = idx >> 3, c16 = idx & 7;
            cp_async16(sb + SW(row * 128 + c16 * 16),
                       qg + (size_t)row * RS + c16 * 8);
        }
    }
    CP_COMMIT(); CP_WAIT0();
    __syncthreads();
    uint32_t qh[2][4][4];
    #pragma unroll
    for (int mt = 0; mt < 2; mt++)
        #pragma unroll
        for (int ks = 0; ks < 4; ks++) {
            int row = w * 32 + mt * 16 + (lid & 15);
            ldsm_x4(sb + SW(row * 128 + ks * 32 + ((lid >> 4) << 4)),
                    qh[mt][ks][0], qh[mt][ks][1], qh[mt][ks][2], qh[mt][ks][3]);
        }
    __syncthreads();

    auto load_kv = [&](int kt, int buf) {
        const __half* kh_g = qkvh + (bT + kt * 64) * RS + CC + h * DH;
        const __half* vh_g = kh_g + CC;
        const uint32_t base = sb + (uint32_t)(buf * KVBUF);
        #pragma unroll
        for (int j = 0; j < 8; j++) {
            int idx = tid + j * 128;
            int half = idx >> 9;
            int r = idx & 511;
            int row = r >> 3, c16 = r & 7;
            uint32_t sw = SW(row * 128 + c16 * 16);
            const __half* src = (half ? vh_g : kh_g) + (size_t)row * RS + c16 * 8;
            cp_async16(base + (uint32_t)(half << 13) + sw, src);
        }
    };

    float o[2][8][4];
    #pragma unroll
    for (int mt = 0; mt < 2; mt++)
        #pragma unroll
        for (int nt = 0; nt < 8; nt++)
            #pragma unroll
            for (int e = 0; e < 4; e++) o[mt][nt][e] = 0.f;
    float m[2][2], l[2][2];
    #pragma unroll
    for (int mt = 0; mt < 2; mt++) {
        m[mt][0] = -CUDART_INF_F; m[mt][1] = -CUDART_INF_F;
        l[mt][0] = 0.f; l[mt][1] = 0.f;
    }
    const int gr0 = qt * 128 + w * 32;
    const int r0 = (lid >> 2);
    const int cbase = (lid & 3) << 1;

    const int kt_max = 2 * qt + 1;
    load_kv(0, 0); CP_COMMIT();
    if (kt_max >= 1) { load_kv(1, 1); CP_COMMIT(); }

    for (int kt = 0; kt <= kt_max; kt++) {
        const int buf = kt % 3;
        const uint32_t tb = sb + (uint32_t)(buf * KVBUF);
        if (kt + 1 <= kt_max) CP_WAIT1(); else CP_WAIT0();
        __syncthreads();
        if (kt + 2 <= kt_max) { load_kv(kt + 2, (kt + 2) % 3); CP_COMMIT(); }

        if (kt * 64 <= gr0 + 31) {                // tile not fully masked
            // S_raw = Qh Kh^T  (32 x 64 per warp)
            float s[2][8][4];
            #pragma unroll
            for (int mt = 0; mt < 2; mt++)
                #pragma unroll
                for (int nt = 0; nt < 8; nt++)
                    #pragma unroll
                    for (int e = 0; e < 4; e++) s[mt][nt][e] = 0.f;

            #pragma unroll
            for (int ks = 0; ks < 4; ks++) {
                #pragma unroll
                for (int ntp = 0; ntp < 4; ntp++) {
                    int rowb = ntp * 16 + ((lid >> 4) << 3) + (lid & 7);
                    uint32_t offb = SW(rowb * 128 + ks * 32 + (((lid >> 3) & 1) << 4));
                    uint32_t kh[4];
                    ldsm_x4(tb + offb, kh[0], kh[1], kh[2], kh[3]);
                    #pragma unroll
                    for (int half = 0; half < 2; half++) {
                        int nt = ntp * 2 + half;
                        #pragma unroll
                        for (int mt = 0; mt < 2; mt++)
                            mma_f16(s[mt][nt],
                                    qh[mt][ks][0], qh[mt][ks][1],
                                    qh[mt][ks][2], qh[mt][ks][3],
                                    kh[half * 2], kh[half * 2 + 1]);
                    }
                }
            }

            // causal mask on raw scores (diagonal-overlapping tiles only)
            if (kt * 64 + 63 > gr0) {
                #pragma unroll
                for (int mt = 0; mt < 2; mt++) {
                    int gr = gr0 + mt * 16 + r0;
                    #pragma unroll
                    for (int nt = 0; nt < 8; nt++) {
                        int gc = kt * 64 + nt * 8 + cbase;
                        if (gc     > gr)     s[mt][nt][0] = -CUDART_INF_F;
                        if (gc + 1 > gr)     s[mt][nt][1] = -CUDART_INF_F;
                        if (gc     > gr + 8) s[mt][nt][2] = -CUDART_INF_F;
                        if (gc + 1 > gr + 8) s[mt][nt][3] = -CUDART_INF_F;
                    }
                }
            }

            // row max (raw), running max (log2 domain), alpha, o-rescale
            float mn[2][2], al[2][2];
            #pragma unroll
            for (int mt = 0; mt < 2; mt++) {
                float mx0 = -CUDART_INF_F, mx1 = -CUDART_INF_F;
                #pragma unroll
                for (int nt = 0; nt < 8; nt++) {
                    mx0 = fmaxf(mx0, fmaxf(s[mt][nt][0], s[mt][nt][1]));
                    mx1 = fmaxf(mx1, fmaxf(s[mt][nt][2], s[mt][nt][3]));
                }
                mx0 = fmaxf(mx0, __shfl_xor_sync(0xffffffffu, mx0, 1));
                mx0 = fmaxf(mx0, __shfl_xor_sync(0xffffffffu, mx0, 2));
                mx1 = fmaxf(mx1, __shfl_xor_sync(0xffffffffu, mx1, 1));
                mx1 = fmaxf(mx1, __shfl_xor_sync(0xffffffffu, mx1, 2));
                mn[mt][0] = fmaxf(m[mt][0], mx0 * SCL);
                mn[mt][1] = fmaxf(m[mt][1], mx1 * SCL);
                al[mt][0] = exp2f(m[mt][0] - mn[mt][0]);
                al[mt][1] = exp2f(m[mt][1] - mn[mt][1]);
                m[mt][0] = mn[mt][0];  m[mt][1] = mn[mt][1];
                #pragma unroll
                for (int nt = 0; nt < 8; nt++) {
                    o[mt][nt][0] *= al[mt][0]; o[mt][nt][1] *= al[mt][0];
                    o[mt][nt][2] *= al[mt][1]; o[mt][nt][3] *= al[mt][1];
                }
            }

            // PV with inline P = ex2(pack(s*SCL - mn)); row sums via ones-mma
            float ssum[2][4];
            #pragma unroll
            for (int mt = 0; mt < 2; mt++)
                #pragma unroll
                for (int e = 0; e < 4; e++) ssum[mt][e] = 0.f;

            #pragma unroll
            for (int ks = 0; ks < 4; ks++) {
                uint32_t ph[2][4];
                #pragma unroll
                for (int mt = 0; mt < 2; mt++) {
                    const int t0 = ks * 2, t1 = ks * 2 + 1;
                    float n0 = mn[mt][0], n1 = mn[mt][1];
                    ph[mt][0] = ex2_f16x2(pack_f16x2(
                        fmaf(s[mt][t0][0], SCL, -n0), fmaf(s[mt][t0][1], SCL, -n0)));
                    ph[mt][1] = ex2_f16x2(pack_f16x2(
                        fmaf(s[mt][t0][2], SCL, -n1), fmaf(s[mt][t0][3], SCL, -n1)));
                    ph[mt][2] = ex2_f16x2(pack_f16x2(
                        fmaf(s[mt][t1][0], SCL, -n0), fmaf(s[mt][t1][1], SCL, -n0)));
                    ph[mt][3] = ex2_f16x2(pack_f16x2(
                        fmaf(s[mt][t1][2], SCL, -n1), fmaf(s[mt][t1][3], SCL, -n1)));
                    mma_f16(ssum[mt], ph[mt][0], ph[mt][1], ph[mt][2], ph[mt][3],
                            ONES_F16X2, ONES_F16X2);
                }
                int rowv = ks * 16 + (lid & 15);
                #pragma unroll
                for (int nt2 = 0; nt2 < 4; nt2++) {
                    uint32_t offv = SW(rowv * 128 + nt2 * 32 + ((lid >> 4) << 4));
                    uint32_t vh[4];
                    ldsm_x4t(tb + 8192 + offv, vh[0], vh[1], vh[2], vh[3]);
                    #pragma unroll
                    for (int mt = 0; mt < 2; mt++) {
                        mma_f16(o[mt][nt2 * 2],     ph[mt][0], ph[mt][1],
                                ph[mt][2], ph[mt][3], vh[0], vh[1]);
                        mma_f16(o[mt][nt2 * 2 + 1], ph[mt][0], ph[mt][1],
                                ph[mt][2], ph[mt][3], vh[2], vh[3]);
                    }
                }
            }

            #pragma unroll
            for (int mt = 0; mt < 2; mt++) {
                l[mt][0] = l[mt][0] * al[mt][0] + ssum[mt][0];
                l[mt][1] = l[mt][1] * al[mt][1] + ssum[mt][2];
            }
        }
        __syncthreads();
    }

    // Epilogue: normalize, fp16 out
    #pragma unroll
    for (int mt = 0; mt < 2; mt++) {
        float i0 = 1.f / l[mt][0], i1 = 1.f / l[mt][1];
        size_t row0 = (bT + (size_t)(qt * 128 + w * 32 + mt * 16 + r0)) * CC + h * DH;
        size_t row1 = row0 + (size_t)8 * CC;
        #pragma unroll
        for (int nt = 0; nt < 8; nt++) {
            int n = nt * 8 + cbase;
            *(half2*)(yh + row0 + n) =
                __floats2half2_rn(o[mt][nt][0] * i0, o[mt][nt][1] * i0);
            *(half2*)(yh + row1 + n) =
                __floats2half2_rn(o[mt][nt][2] * i1, o[mt][nt][3] * i1);
        }
    }
}

// ---------------------------------------------------------------------------
extern "C" void kernel_launch(void* const* d_in, const int* in_sizes, int n_in,
                              void* d_out, int out_size)
{
    const float* x      = (const float*)d_in[0];
    const float* W_attn = (const float*)d_in[1];
    const float* b_attn = (const float*)d_in[2];
    const float* W_proj = (const float*)d_in[3];
    const float* b_proj = (const float*)d_in[4];
    float* out = (float*)d_out;

    __half *xh, *qkvh, *yh, *wah, *wph;
    cudaGetSymbolAddress((void**)&xh, g_xh);
    cudaGetSymbolAddress((void**)&qkvh, g_qkvh);
    cudaGetSymbolAddress((void**)&yh, g_yh);
    cudaGetSymbolAddress((void**)&wah, g_wah);
    cudaGetSymbolAddress((void**)&wph, g_wph);

    const int M = BB * TT;       // 4096
    const int N1 = 3 * CC;       // 3072
    const int N2 = CC;           // 1024
    const int K = CC;            // 1024

    cudaFuncSetAttribute(gemm_mma<true>,
                         cudaFuncAttributeMaxDynamicSharedMemorySize, GSMEM);
    cudaFuncSetAttribute(gemm_mma<false>,
                         cudaFuncAttributeMaxDynamicSharedMemorySize, GSMEM);
    cudaFuncSetAttribute(attn_mma,
                         cudaFuncAttributeMaxDynamicSharedMemorySize, ATT_SMEM);

    // Prep: x -> fp16; both weights -> transposed fp16 (single launch)
    cvt_half<<<(M * K / 2 + 255) / 256, 256>>>(x, xh, M * K / 2);
    {
        dim3 grid(96 + 32, 32), blk(32, 8);
        cvt_t2<<<grid, blk>>>(W_attn, wah, W_proj, wph);
    }

    // 1) qkv = x @ W_attn + b_attn  (fp16)
    {
        dim3 grid(N1 / 256, M / 128);
        gemm_mma<true><<<grid, 256, GSMEM>>>(xh, wah, b_attn,
                                             nullptr, qkvh, N1, K);
    }

    // 2) Flash attention -> y (fp16)
    {
        dim3 grid(TT / 128, HH, BB);
        attn_mma<<<grid, 128, ATT_SMEM>>>(qkvh, yh);
    }

    // 3) out = y @ W_proj + b_proj (fp32)
    {
        dim3 grid(N2 / 256, M / 128);
        gemm_mma<false><<<grid, 256, GSMEM>>>(yh, wph, b_proj,
                                              out, nullptr, N2, K);
    }
}

// round 15
// speedup vs baseline: 1.0901x; 1.0251x over previous
#include <cuda_runtime.h>
#include <cuda_fp16.h>
#include <math_constants.h>
#include <cstdint>

// Problem constants
#define TT 2048
#define CC 1024
#define HH 16
#define DH 64
#define BB 2

#define SW(off) ((uint32_t)(off) ^ ((((uint32_t)(off)) >> 3) & 0x70u))

// ---------------------------------------------------------------------------
// PTX helpers (base-target safe)
// ---------------------------------------------------------------------------
__device__ __forceinline__ uint32_t smem_u32(const void* p) {
    uint32_t a;
    asm("{ .reg .u64 t; cvta.to.shared.u64 t, %1; cvt.u32.u64 %0, t; }"
        : "=r"(a) : "l"(p));
    return a;
}
__device__ __forceinline__ void ldsm_x4(uint32_t addr, uint32_t &r0, uint32_t &r1,
                                        uint32_t &r2, uint32_t &r3) {
    asm volatile("ldmatrix.sync.aligned.m8n8.x4.shared.b16 {%0,%1,%2,%3}, [%4];"
                 : "=r"(r0), "=r"(r1), "=r"(r2), "=r"(r3) : "r"(addr));
}
__device__ __forceinline__ void ldsm_x4t(uint32_t addr, uint32_t &r0, uint32_t &r1,
                                         uint32_t &r2, uint32_t &r3) {
    asm volatile("ldmatrix.sync.aligned.m8n8.x4.trans.shared.b16 {%0,%1,%2,%3}, [%4];"
                 : "=r"(r0), "=r"(r1), "=r"(r2), "=r"(r3) : "r"(addr));
}
__device__ __forceinline__ void mma_f16(float* c, uint32_t a0, uint32_t a1,
                                        uint32_t a2, uint32_t a3,
                                        uint32_t b0, uint32_t b1) {
    asm volatile("mma.sync.aligned.m16n8k16.row.col.f32.f16.f16.f32 "
                 "{%0,%1,%2,%3}, {%4,%5,%6,%7}, {%8,%9}, {%0,%1,%2,%3};"
                 : "+f"(c[0]), "+f"(c[1]), "+f"(c[2]), "+f"(c[3])
                 : "r"(a0), "r"(a1), "r"(a2), "r"(a3), "r"(b0), "r"(b1));
}
__device__ __forceinline__ void cp_async16(uint32_t dst, const void* src) {
    asm volatile("cp.async.cg.shared.global [%0], [%1], 16;"
                 :: "r"(dst), "l"(src) : "memory");
}
#define CP_COMMIT() asm volatile("cp.async.commit_group;" ::: "memory")
#define CP_WAIT0()  asm volatile("cp.async.wait_group 0;" ::: "memory")
#define CP_WAIT1()  asm volatile("cp.async.wait_group 1;" ::: "memory")

__device__ __forceinline__ uint32_t pack_f16x2(float lo, float hi) {
    uint32_t d;
    asm("cvt.rn.f16x2.f32 %0, %1, %2;" : "=r"(d) : "f"(hi), "f"(lo));
    return d;
}
__device__ __forceinline__ uint32_t ex2_f16x2(uint32_t a) {
    uint32_t d;
    asm("ex2.approx.f16x2 %0, %1;" : "=r"(d) : "r"(a));
    return d;
}

// ---------------------------------------------------------------------------
// Scratch
// ---------------------------------------------------------------------------
__device__ __half g_xh[(size_t)BB * TT * CC];
__device__ __half g_qkvh[(size_t)BB * TT * 3 * CC];
__device__ __half g_yh[(size_t)BB * TT * CC];
__device__ __half g_wah[(size_t)3 * CC * CC];          // W_attn^T [3C, C] fp16
__device__ __half g_wph[(size_t)CC * CC];              // W_proj^T [C, C]  fp16

// ---------------------------------------------------------------------------
// Fused prep: weights fp32 [K,N] -> fp16 transposed [N,K]  (bx < 128)
//             x fp32 -> fp16                                (bx >= 128)
// grid (160, 32), block (32, 8)
// ---------------------------------------------------------------------------
__global__ __launch_bounds__(256) void cvt_all(
    const float* __restrict__ Wa, __half* __restrict__ wah,
    const float* __restrict__ Wp, __half* __restrict__ wph,
    const float* __restrict__ Xf, __half* __restrict__ Xh)
{
    __shared__ float ts[32][33];
    int tx = threadIdx.x, ty = threadIdx.y;
    int bx = blockIdx.x, by = blockIdx.y;
    const int tid = ty * 32 + tx;

    if (bx >= 128) {
        // x conversion: 2M half2 elems over 32x32x256 threads, 8 each
        int lin = ((bx - 128) * 32 + by) * 256 + tid;
        const float2* xin = (const float2*)Xf;
        half2* xout = (half2*)Xh;
        #pragma unroll
        for (int j = 0; j < 8; j++) {
            int i = lin + j * 262144;
            float2 v = xin[i];
            xout[i] = __floats2half2_rn(v.x, v.y);
        }
        return;
    }

    const float* in;
    __half* out;
    int N;
    if (bx < 96) { in = Wa; out = wah; N = 3 * CC; }
    else         { in = Wp; out = wph; N = CC; bx -= 96; }
    const int K = CC;
    #pragma unroll
    for (int j = 0; j < 4; j++) {
        int k = by * 32 + ty + j * 8;
        ts[ty + j * 8][tx] = in[(size_t)k * N + bx * 32 + tx];
    }
    __syncthreads();
    #pragma unroll
    for (int j = 0; j < 4; j++) {
        int nrow = bx * 32 + ty + j * 8;
        out[(size_t)nrow * K + by * 32 + tx] = __float2half(ts[tx][ty + j * 8]);
    }
}

// ---------------------------------------------------------------------------
// Tensor-core GEMM (large tile), fp16: C = Ah @ Bh^T + bias
// CTA 128x256, 8 warps of 64x64, k128 chunks, 2-stage cp.async, 1 CTA/SM.
// Used for QKV (grid 12x32 = 384 CTAs).
// ---------------------------------------------------------------------------
#define STG_BYTES 98304
#define GSMEM (2 * STG_BYTES + 2048)

template<bool HALF_OUT>
__global__ __launch_bounds__(256, 1) void gemm_mma(
    const __half* __restrict__ Ah, const __half* __restrict__ Bh,
    const float* __restrict__ bias, float* __restrict__ Cf,
    __half* __restrict__ Ch, int Ncols, int K)
{
    extern __shared__ char dsm[];
    const uint32_t sb = (smem_u32(dsm) + 1023u) & ~1023u;
    float* bias_s = (float*)(dsm + ((sb - smem_u32(dsm)) + 2 * STG_BYTES));

    const int tid = threadIdx.x;
    const int lid = tid & 31;
    const int wid = tid >> 5;
    const int wm = (wid >> 2) * 64;
    const int wn = (wid & 3) * 64;
    const int bm = blockIdx.y * 128;
    const int bn = blockIdx.x * 256;

    bias_s[tid] = bias[bn + tid];

    float c[4][8][4];
    #pragma unroll
    for (int mt = 0; mt < 4; mt++)
        #pragma unroll
        for (int nt = 0; nt < 8; nt++)
            #pragma unroll
            for (int e = 0; e < 4; e++) c[mt][nt][e] = 0.f;

    auto load_chunk = [&](int ch, int stg) {
        const int k0 = ch << 7;
        const uint32_t base = sb + (uint32_t)(stg * STG_BYTES);
        #pragma unroll
        for (int j = 0; j < 8; j++) {          // A
            int idx = tid + j * 256;
            int row = idx >> 4;
            int c16f = idx & 15;
            int sub = c16f >> 3, c16 = c16f & 7;
            cp_async16(base + (uint32_t)(sub << 14) + SW(row * 128 + c16 * 16),
                       Ah + (size_t)(bm + row) * K + k0 + sub * 64 + c16 * 8);
        }
        #pragma unroll
        for (int j = 0; j < 16; j++) {         // B
            int idx = tid + j * 256;
            int row = idx >> 4;
            int c16f = idx & 15;
            int sub = c16f >> 3, c16 = c16f & 7;
            cp_async16(base + 32768u + (uint32_t)(sub << 15) + SW(row * 128 + c16 * 16),
                       Bh + (size_t)(bn + row) * K + k0 + sub * 64 + c16 * 8);
        }
    };

    auto compute = [&](int stg) {
        const uint32_t tb = sb + (uint32_t)(stg * STG_BYTES);
        #pragma unroll
        for (int ks = 0; ks < 8; ks++) {
            const int sub = ks >> 2, ksl = ks & 3;
            const uint32_t abase = tb + (uint32_t)(sub << 14);
            const uint32_t bbase = tb + 32768u + (uint32_t)(sub << 15);
            uint32_t ah[4][4];
            #pragma unroll
            for (int mt = 0; mt < 4; mt++) {
                int row = wm + mt * 16 + (lid & 15);
                ldsm_x4(abase + SW(row * 128 + ksl * 32 + ((lid >> 4) << 4)),
                        ah[mt][0], ah[mt][1], ah[mt][2], ah[mt][3]);
            }
            #pragma unroll
            for (int ntp = 0; ntp < 4; ntp++) {
                int rowb = wn + ntp * 16 + ((lid >> 4) << 3) + (lid & 7);
                uint32_t offb = SW(rowb * 128 + ksl * 32 + (((lid >> 3) & 1) << 4));
                uint32_t bh[4];
                ldsm_x4(bbase + offb, bh[0], bh[1], bh[2], bh[3]);
                #pragma unroll
                for (int half = 0; half < 2; half++) {
                    int nt = ntp * 2 + half;
                    #pragma unroll
                    for (int mt = 0; mt < 4; mt++)
                        mma_f16(c[mt][nt], ah[mt][0], ah[mt][1], ah[mt][2], ah[mt][3],
                                bh[half * 2], bh[half * 2 + 1]);
                }
            }
        }
    };

    const int nch = K >> 7;                 // 8 chunks for K=1024
    load_chunk(0, 0); CP_COMMIT();

    for (int ch = 0; ch < nch; ch++) {
        CP_WAIT0();
        __syncthreads();
        if (ch + 1 < nch) { load_chunk(ch + 1, (ch + 1) & 1); CP_COMMIT(); }
        compute(ch & 1);
    }

    #pragma unroll
    for (int mt = 0; mt < 4; mt++) {
        #pragma unroll
        for (int nt = 0; nt < 8; nt++) {
            int m0 = bm + wm + mt * 16 + (lid >> 2);
            int nl = wn + nt * 8 + ((lid & 3) << 1);
            int n  = bn + nl;
            float b0 = bias_s[nl], b1 = bias_s[nl + 1];
            float v00 = c[mt][nt][0] + b0, v01 = c[mt][nt][1] + b1;
            float v10 = c[mt][nt][2] + b0, v11 = c[mt][nt][3] + b1;
            if (HALF_OUT) {
                *(half2*)(Ch + (size_t)m0 * Ncols + n) =
                    __floats2half2_rn(v00, v01);
                *(half2*)(Ch + (size_t)(m0 + 8) * Ncols + n) =
                    __floats2half2_rn(v10, v11);
            } else {
                float2 p0 = {v00, v01}, p1 = {v10, v11};
                *(float2*)(Cf + (size_t)m0 * Ncols + n) = p0;
                *(float2*)(Cf + (size_t)(m0 + 8) * Ncols + n) = p1;
            }
        }
    }
}

// ---------------------------------------------------------------------------
// Tensor-core GEMM (small tile), fp16: C = Ah @ Bh^T + bias (fp32 out)
// CTA 128x128, 8 warps of 64x32, k64 chunks, 3-stage cp.async, 2 CTAs/SM.
// Used for proj (grid 8x32 = 256 CTAs -> full SM coverage, small quantum).
// ---------------------------------------------------------------------------
#define SSTG_BYTES 32768
#define GSMEM_SM (3 * SSTG_BYTES + 2048)

__global__ __launch_bounds__(256, 2) void gemm_mma_sm(
    const __half* __restrict__ Ah, const __half* __restrict__ Bh,
    const float* __restrict__ bias, float* __restrict__ Cf,
    int Ncols, int K)
{
    extern __shared__ char dsm[];
    const uint32_t sb = (smem_u32(dsm) + 1023u) & ~1023u;
    float* bias_s = (float*)(dsm + ((sb - smem_u32(dsm)) + 3 * SSTG_BYTES));

    const int tid = threadIdx.x;
    const int lid = tid & 31;
    const int wid = tid >> 5;
    const int wm = (wid >> 2) * 64;
    const int wn = (wid & 3) * 32;
    const int bm = blockIdx.y * 128;
    const int bn = blockIdx.x * 128;

    if (tid < 128) bias_s[tid] = bias[bn + tid];

    float c[4][4][4];
    #pragma unroll
    for (int mt = 0; mt < 4; mt++)
        #pragma unroll
        for (int nt = 0; nt < 4; nt++)
            #pragma unroll
            for (int e = 0; e < 4; e++) c[mt][nt][e] = 0.f;

    auto load_chunk = [&](int ch, int stg) {
        const int k0 = ch << 6;
        const uint32_t base = sb + (uint32_t)(stg * SSTG_BYTES);
        #pragma unroll
        for (int j = 0; j < 8; j++) {
            int idx = tid + j * 256;
            int reg = idx >> 10;
            int row = (idx >> 3) & 127;
            int c16 = idx & 7;
            uint32_t dst = base + (uint32_t)(reg << 14) + SW(row * 128 + c16 * 16);
            int kc = k0 + c16 * 8;
            const __half* src = (reg == 0)
                ? Ah + (size_t)(bm + row) * K + kc
                : Bh + (size_t)(bn + row) * K + kc;
            cp_async16(dst, src);
        }
    };

    auto compute = [&](int stg) {
        const uint32_t tb = sb + (uint32_t)(stg * SSTG_BYTES);
        #pragma unroll
        for (int ks = 0; ks < 4; ks++) {
            uint32_t ah[4][4];
            #pragma unroll
            for (int mt = 0; mt < 4; mt++) {
                int row = wm + mt * 16 + (lid & 15);
                ldsm_x4(tb + SW(row * 128 + ks * 32 + ((lid >> 4) << 4)),
                        ah[mt][0], ah[mt][1], ah[mt][2], ah[mt][3]);
            }
            #pragma unroll
            for (int ntp = 0; ntp < 2; ntp++) {
                int rowb = wn + ntp * 16 + ((lid >> 4) << 3) + (lid & 7);
                uint32_t offb = SW(rowb * 128 + ks * 32 + (((lid >> 3) & 1) << 4));
                uint32_t bh[4];
                ldsm_x4(tb + 16384 + offb, bh[0], bh[1], bh[2], bh[3]);
                #pragma unroll
                for (int half = 0; half < 2; half++) {
                    int nt = ntp * 2 + half;
                    #pragma unroll
                    for (int mt = 0; mt < 4; mt++)
                        mma_f16(c[mt][nt], ah[mt][0], ah[mt][1], ah[mt][2], ah[mt][3],
                                bh[half * 2], bh[half * 2 + 1]);
                }
            }
        }
    };

    const int nch = K >> 6;                 // 16 chunks for K=1024
    load_chunk(0, 0); CP_COMMIT();
    load_chunk(1, 1); CP_COMMIT();

    int stg = 0;
    for (int ch = 0; ch < nch; ch++) {
        if (ch + 2 < nch) CP_WAIT1(); else CP_WAIT0();
        __syncthreads();
        if (ch + 2 < nch) { load_chunk(ch + 2, (stg + 2) % 3); CP_COMMIT(); }
        compute(stg);
        stg = (stg + 1) % 3;
    }

    #pragma unroll
    for (int mt = 0; mt < 4; mt++) {
        #pragma unroll
        for (int nt = 0; nt < 4; nt++) {
            int m0 = bm + wm + mt * 16 + (lid >> 2);
            int nl = wn + nt * 8 + ((lid & 3) << 1);
            int n  = bn + nl;
            float b0 = bias_s[nl], b1 = bias_s[nl + 1];
            float2 p0 = {c[mt][nt][0] + b0, c[mt][nt][1] + b1};
            float2 p1 = {c[mt][nt][2] + b0, c[mt][nt][3] + b1};
            *(float2*)(Cf + (size_t)m0 * Ncols + n) = p0;
            *(float2*)(Cf + (size_t)(m0 + 8) * Ncols + n) = p1;
        }
    }
}

// ---------------------------------------------------------------------------
// Flash attention (causal), fp16: S = Qh Kh^T; O += P Vh.
// Block = (b, h, q-tile 128). 4 warps of 32 q-rows, 2 CTAs/SM.
// 3-stage KV pipeline (16KB each: Kh 0 | Vh 8K).
// Softmax: P = ex2.approx.f16x2(pack(s*SCL - mn)); row-sums via ones-mma.
// (R12/R14 configuration — measured optimum.)
// ---------------------------------------------------------------------------
#define KVBUF 16384
#define ATT_SMEM (1024 + 3 * KVBUF)
#define ONES_F16X2 0x3C003C00u

__global__ __launch_bounds__(128, 2) void attn_mma(
    const __half* __restrict__ qkvh, __half* __restrict__ yh)
{
    extern __shared__ char asm_[];
    const uint32_t sb = (smem_u32(asm_) + 1023u) & ~1023u;

    const int tid = threadIdx.x;
    const int lid = tid & 31;
    const int w = tid >> 5;
    const int qt = gridDim.x - 1 - blockIdx.x;    // longest first
    const int h = blockIdx.y;
    const int b = blockIdx.z;
    const size_t bT = (size_t)b * TT;
    const int RS = 3 * CC;
    const float SCL = 0.18033688f;                // 0.125 * log2(e)

    // ---- stage Q (128 x 64 fp16 = 16KB) into buffer0, extract fragments
    {
        const __half* qg = qkvh + (bT + qt * 128) * RS + h * DH;
        #pragma unroll
        for (int j = 0; j < 8; j++) {
            int idx = tid + j * 128;
            int row = idx >> 3, c16 = idx & 7;
            cp_async16(sb + SW(row * 128 + c16 * 16),
                       qg + (size_t)row * RS + c16 * 8);
        }
    }
    CP_COMMIT(); CP_WAIT0();
    __syncthreads();
    uint32_t qh[2][4][4];
    #pragma unroll
    for (int mt = 0; mt < 2; mt++)
        #pragma unroll
        for (int ks = 0; ks < 4; ks++) {
            int row = w * 32 + mt * 16 + (lid & 15);
            ldsm_x4(sb + SW(row * 128 + ks * 32 + ((lid >> 4) << 4)),
                    qh[mt][ks][0], qh[mt][ks][1], qh[mt][ks][2], qh[mt][ks][3]);
        }
    __syncthreads();

    auto load_kv = [&](int kt, int buf) {
        const __half* kh_g = qkvh + (bT + kt * 64) * RS + CC + h * DH;
        const __half* vh_g = kh_g + CC;
        const uint32_t base = sb + (uint32_t)(buf * KVBUF);
        #pragma unroll
        for (int j = 0; j < 8; j++) {
            int idx = tid + j * 128;
            int half = idx >> 9;
            int r = idx & 511;
            int row = r >> 3, c16 = r & 7;
            uint32_t sw = SW(row * 128 + c16 * 16);
            const __half* src = (half ? vh_g : kh_g) + (size_t)row * RS + c16 * 8;
            cp_async16(base + (uint32_t)(half << 13) + sw, src);
        }
    };

    float o[2][8][4];
    #pragma unroll
    for (int mt = 0; mt < 2; mt++)
        #pragma unroll
        for (int nt = 0; nt < 8; nt++)
            #pragma unroll
            for (int e = 0; e < 4; e++) o[mt][nt][e] = 0.f;
    float m[2][2], l[2][2];
    #pragma unroll
    for (int mt = 0; mt < 2; mt++) {
        m[mt][0] = -CUDART_INF_F; m[mt][1] = -CUDART_INF_F;
        l[mt][0] = 0.f; l[mt][1] = 0.f;
    }
    const int gr0 = qt * 128 + w * 32;
    const int r0 = (lid >> 2);
    const int cbase = (lid & 3) << 1;

    const int kt_max = 2 * qt + 1;
    load_kv(0, 0); CP_COMMIT();
    if (kt_max >= 1) { load_kv(1, 1); CP_COMMIT(); }

    for (int kt = 0; kt <= kt_max; kt++) {
        const int buf = kt % 3;
        const uint32_t tb = sb + (uint32_t)(buf * KVBUF);
        if (kt + 1 <= kt_max) CP_WAIT1(); else CP_WAIT0();
        __syncthreads();
        if (kt + 2 <= kt_max) { load_kv(kt + 2, (kt + 2) % 3); CP_COMMIT(); }

        if (kt * 64 <= gr0 + 31) {                // tile not fully masked
            // S_raw = Qh Kh^T  (32 x 64 per warp)
            float s[2][8][4];
            #pragma unroll
            for (int mt = 0; mt < 2; mt++)
                #pragma unroll
                for (int nt = 0; nt < 8; nt++)
                    #pragma unroll
                    for (int e = 0; e < 4; e++) s[mt][nt][e] = 0.f;

            #pragma unroll
            for (int ks = 0; ks < 4; ks++) {
                #pragma unroll
                for (int ntp = 0; ntp < 4; ntp++) {
                    int rowb = ntp * 16 + ((lid >> 4) << 3) + (lid & 7);
                    uint32_t offb = SW(rowb * 128 + ks * 32 + (((lid >> 3) & 1) << 4));
                    uint32_t kh[4];
                    ldsm_x4(tb + offb, kh[0], kh[1], kh[2], kh[3]);
                    #pragma unroll
                    for (int half = 0; half < 2; half++) {
                        int nt = ntp * 2 + half;
                        #pragma unroll
                        for (int mt = 0; mt < 2; mt++)
                            mma_f16(s[mt][nt],
                                    qh[mt][ks][0], qh[mt][ks][1],
                                    qh[mt][ks][2], qh[mt][ks][3],
                                    kh[half * 2], kh[half * 2 + 1]);
                    }
                }
            }

            // causal mask on raw scores (diagonal-overlapping tiles only)
            if (kt * 64 + 63 > gr0) {
                #pragma unroll
                for (int mt = 0; mt < 2; mt++) {
                    int gr = gr0 + mt * 16 + r0;
                    #pragma unroll
                    for (int nt = 0; nt < 8; nt++) {
                        int gc = kt * 64 + nt * 8 + cbase;
                        if (gc     > gr)     s[mt][nt][0] = -CUDART_INF_F;
                        if (gc + 1 > gr)     s[mt][nt][1] = -CUDART_INF_F;
                        if (gc     > gr + 8) s[mt][nt][2] = -CUDART_INF_F;
                        if (gc + 1 > gr + 8) s[mt][nt][3] = -CUDART_INF_F;
                    }
                }
            }

            // row max (raw), running max (log2 domain), alpha, o-rescale
            float mn[2][2], al[2][2];
            #pragma unroll
            for (int mt = 0; mt < 2; mt++) {
                float mx0 = -CUDART_INF_F, mx1 = -CUDART_INF_F;
                #pragma unroll
                for (int nt = 0; nt < 8; nt++) {
                    mx0 = fmaxf(mx0, fmaxf(s[mt][nt][0], s[mt][nt][1]));
                    mx1 = fmaxf(mx1, fmaxf(s[mt][nt][2], s[mt][nt][3]));
                }
                mx0 = fmaxf(mx0, __shfl_xor_sync(0xffffffffu, mx0, 1));
                mx0 = fmaxf(mx0, __shfl_xor_sync(0xffffffffu, mx0, 2));
                mx1 = fmaxf(mx1, __shfl_xor_sync(0xffffffffu, mx1, 1));
                mx1 = fmaxf(mx1, __shfl_xor_sync(0xffffffffu, mx1, 2));
                mn[mt][0] = fmaxf(m[mt][0], mx0 * SCL);
                mn[mt][1] = fmaxf(m[mt][1], mx1 * SCL);
                al[mt][0] = exp2f(m[mt][0] - mn[mt][0]);
                al[mt][1] = exp2f(m[mt][1] - mn[mt][1]);
                m[mt][0] = mn[mt][0];  m[mt][1] = mn[mt][1];
                #pragma unroll
                for (int nt = 0; nt < 8; nt++) {
                    o[mt][nt][0] *= al[mt][0]; o[mt][nt][1] *= al[mt][0];
                    o[mt][nt][2] *= al[mt][1]; o[mt][nt][3] *= al[mt][1];
                }
            }

            // PV with inline P = ex2(pack(s*SCL - mn)); row sums via ones-mma
            float ssum[2][4];
            #pragma unroll
            for (int mt = 0; mt < 2; mt++)
                #pragma unroll
                for (int e = 0; e < 4; e++) ssum[mt][e] = 0.f;

            #pragma unroll
            for (int ks = 0; ks < 4; ks++) {
                uint32_t ph[2][4];
                #pragma unroll
                for (int mt = 0; mt < 2; mt++) {
                    const int t0 = ks * 2, t1 = ks * 2 + 1;
                    float n0 = mn[mt][0], n1 = mn[mt][1];
                    ph[mt][0] = ex2_f16x2(pack_f16x2(
                        fmaf(s[mt][t0][0], SCL, -n0), fmaf(s[mt][t0][1], SCL, -n0)));
                    ph[mt][1] = ex2_f16x2(pack_f16x2(
                        fmaf(s[mt][t0][2], SCL, -n1), fmaf(s[mt][t0][3], SCL, -n1)));
                    ph[mt][2] = ex2_f16x2(pack_f16x2(
                        fmaf(s[mt][t1][0], SCL, -n0), fmaf(s[mt][t1][1], SCL, -n0)));
                    ph[mt][3] = ex2_f16x2(pack_f16x2(
                        fmaf(s[mt][t1][2], SCL, -n1), fmaf(s[mt][t1][3], SCL, -n1)));
                    mma_f16(ssum[mt], ph[mt][0], ph[mt][1], ph[mt][2], ph[mt][3],
                            ONES_F16X2, ONES_F16X2);
                }
                int rowv = ks * 16 + (lid & 15);
                #pragma unroll
                for (int nt2 = 0; nt2 < 4; nt2++) {
                    uint32_t offv = SW(rowv * 128 + nt2 * 32 + ((lid >> 4) << 4));
                    uint32_t vh[4];
                    ldsm_x4t(tb + 8192 + offv, vh[0], vh[1], vh[2], vh[3]);
                    #pragma unroll
                    for (int mt = 0; mt < 2; mt++) {
                        mma_f16(o[mt][nt2 * 2],     ph[mt][0], ph[mt][1],
                                ph[mt][2], ph[mt][3], vh[0], vh[1]);
                        mma_f16(o[mt][nt2 * 2 + 1], ph[mt][0], ph[mt][1],
                                ph[mt][2], ph[mt][3], vh[2], vh[3]);
                    }
                }
            }

            #pragma unroll
            for (int mt = 0; mt < 2; mt++) {
                l[mt][0] = l[mt][0] * al[mt][0] + ssum[mt][0];
                l[mt][1] = l[mt][1] * al[mt][1] + ssum[mt][2];
            }
        }
        __syncthreads();
    }

    // Epilogue: normalize, fp16 out
    #pragma unroll
    for (int mt = 0; mt < 2; mt++) {
        float i0 = 1.f / l[mt][0], i1 = 1.f / l[mt][1];
        size_t row0 = (bT + (size_t)(qt * 128 + w * 32 + mt * 16 + r0)) * CC + h * DH;
        size_t row1 = row0 + (size_t)8 * CC;
        #pragma unroll
        for (int nt = 0; nt < 8; nt++) {
            int n = nt * 8 + cbase;
            *(half2*)(yh + row0 + n) =
                __floats2half2_rn(o[mt][nt][0] * i0, o[mt][nt][1] * i0);
            *(half2*)(yh + row1 + n) =
                __floats2half2_rn(o[mt][nt][2] * i1, o[mt][nt][3] * i1);
        }
    }
}

// ---------------------------------------------------------------------------
extern "C" void kernel_launch(void* const* d_in, const int* in_sizes, int n_in,
                              void* d_out, int out_size)
{
    const float* x      = (const float*)d_in[0];
    const float* W_attn = (const float*)d_in[1];
    const float* b_attn = (const float*)d_in[2];
    const float* W_proj = (const float*)d_in[3];
    const float* b_proj = (const float*)d_in[4];
    float* out = (float*)d_out;

    __half *xh, *qkvh, *yh, *wah, *wph;
    cudaGetSymbolAddress((void**)&xh, g_xh);
    cudaGetSymbolAddress((void**)&qkvh, g_qkvh);
    cudaGetSymbolAddress((void**)&yh, g_yh);
    cudaGetSymbolAddress((void**)&wah, g_wah);
    cudaGetSymbolAddress((void**)&wph, g_wph);

    const int M = BB * TT;       // 4096
    const int N1 = 3 * CC;       // 3072
    const int N2 = CC;           // 1024
    const int K = CC;            // 1024

    cudaFuncSetAttribute(gemm_mma<true>,
                         cudaFuncAttributeMaxDynamicSharedMemorySize, GSMEM);
    cudaFuncSetAttribute(gemm_mma_sm,
                         cudaFuncAttributeMaxDynamicSharedMemorySize, GSMEM_SM);
    cudaFuncSetAttribute(attn_mma,
                         cudaFuncAttributeMaxDynamicSharedMemorySize, ATT_SMEM);

    // Prep (single launch): x -> fp16 and both weights -> transposed fp16
    {
        dim3 grid(160, 32), blk(32, 8);
        cvt_all<<<grid, blk>>>(W_attn, wah, W_proj, wph, x, xh);
    }

    // 1) qkv = x @ W_attn + b_attn  (fp16, large-tile GEMM)
    {
        dim3 grid(N1 / 256, M / 128);
        gemm_mma<true><<<grid, 256, GSMEM>>>(xh, wah, b_attn,
                                             nullptr, qkvh, N1, K);
    }

    // 2) Flash attention -> y (fp16)
    {
        dim3 grid(TT / 128, HH, BB);
        attn_mma<<<grid, 128, ATT_SMEM>>>(qkvh, yh);
    }

    // 3) out = y @ W_proj + b_proj (fp32, small-tile GEMM for SM coverage)
    {
        dim3 grid(N2 / 128, M / 128);
        gemm_mma_sm<<<grid, 256, GSMEM_SM>>>(yh, wph, b_proj, out, N2, K);
    }
}

// round 16
// speedup vs baseline: 1.0912x; 1.0010x over previous
#include <cuda_runtime.h>
#include <cuda_fp16.h>
#include <math_constants.h>
#include <cstdint>

// Problem constants
#define TT 2048
#define CC 1024
#define HH 16
#define DH 64
#define BB 2

#define SW(off) ((uint32_t)(off) ^ ((((uint32_t)(off)) >> 3) & 0x70u))

// ---------------------------------------------------------------------------
// PTX helpers (base-target safe)
// ---------------------------------------------------------------------------
__device__ __forceinline__ uint32_t smem_u32(const void* p) {
    uint32_t a;
    asm("{ .reg .u64 t; cvta.to.shared.u64 t, %1; cvt.u32.u64 %0, t; }"
        : "=r"(a) : "l"(p));
    return a;
}
__device__ __forceinline__ void ldsm_x4(uint32_t addr, uint32_t &r0, uint32_t &r1,
                                        uint32_t &r2, uint32_t &r3) {
    asm volatile("ldmatrix.sync.aligned.m8n8.x4.shared.b16 {%0,%1,%2,%3}, [%4];"
                 : "=r"(r0), "=r"(r1), "=r"(r2), "=r"(r3) : "r"(addr));
}
__device__ __forceinline__ void ldsm_x4t(uint32_t addr, uint32_t &r0, uint32_t &r1,
                                         uint32_t &r2, uint32_t &r3) {
    asm volatile("ldmatrix.sync.aligned.m8n8.x4.trans.shared.b16 {%0,%1,%2,%3}, [%4];"
                 : "=r"(r0), "=r"(r1), "=r"(r2), "=r"(r3) : "r"(addr));
}
__device__ __forceinline__ void mma_f16(float* c, uint32_t a0, uint32_t a1,
                                        uint32_t a2, uint32_t a3,
                                        uint32_t b0, uint32_t b1) {
    asm volatile("mma.sync.aligned.m16n8k16.row.col.f32.f16.f16.f32 "
                 "{%0,%1,%2,%3}, {%4,%5,%6,%7}, {%8,%9}, {%0,%1,%2,%3};"
                 : "+f"(c[0]), "+f"(c[1]), "+f"(c[2]), "+f"(c[3])
                 : "r"(a0), "r"(a1), "r"(a2), "r"(a3), "r"(b0), "r"(b1));
}
__device__ __forceinline__ void cp_async16(uint32_t dst, const void* src) {
    asm volatile("cp.async.cg.shared.global [%0], [%1], 16;"
                 :: "r"(dst), "l"(src) : "memory");
}
#define CP_COMMIT() asm volatile("cp.async.commit_group;" ::: "memory")
#define CP_WAIT0()  asm volatile("cp.async.wait_group 0;" ::: "memory")
#define CP_WAIT1()  asm volatile("cp.async.wait_group 1;" ::: "memory")

__device__ __forceinline__ uint32_t pack_f16x2(float lo, float hi) {
    uint32_t d;
    asm("cvt.rn.f16x2.f32 %0, %1, %2;" : "=r"(d) : "f"(hi), "f"(lo));
    return d;
}
__device__ __forceinline__ uint32_t ex2_f16x2(uint32_t a) {
    uint32_t d;
    asm("ex2.approx.f16x2 %0, %1;" : "=r"(d) : "r"(a));
    return d;
}

// ---------------------------------------------------------------------------
// Scratch
// ---------------------------------------------------------------------------
__device__ __half g_xh[(size_t)BB * TT * CC];
__device__ __half g_qkvh[(size_t)BB * TT * 3 * CC];
__device__ __half g_yh[(size_t)BB * TT * CC];
__device__ __half g_wah[(size_t)3 * CC * CC];          // W_attn^T [3C, C] fp16
__device__ __half g_wph[(size_t)CC * CC];              // W_proj^T [C, C]  fp16

// ---------------------------------------------------------------------------
// Fused prep: weights fp32 [K,N] -> fp16 transposed [N,K]  (bx < 128)
//             x fp32 -> fp16                                (bx >= 128)
// grid (160, 32), block (32, 8)
// ---------------------------------------------------------------------------
__global__ __launch_bounds__(256) void cvt_all(
    const float* __restrict__ Wa, __half* __restrict__ wah,
    const float* __restrict__ Wp, __half* __restrict__ wph,
    const float* __restrict__ Xf, __half* __restrict__ Xh)
{
    __shared__ float ts[32][33];
    int tx = threadIdx.x, ty = threadIdx.y;
    int bx = blockIdx.x, by = blockIdx.y;
    const int tid = ty * 32 + tx;

    if (bx >= 128) {
        // x conversion: 2M half2 elems over 32x32x256 threads, 8 each
        int lin = ((bx - 128) * 32 + by) * 256 + tid;
        const float2* xin = (const float2*)Xf;
        half2* xout = (half2*)Xh;
        #pragma unroll
        for (int j = 0; j < 8; j++) {
            int i = lin + j * 262144;
            float2 v = xin[i];
            xout[i] = __floats2half2_rn(v.x, v.y);
        }
        return;
    }

    const float* in;
    __half* out;
    int N;
    if (bx < 96) { in = Wa; out = wah; N = 3 * CC; }
    else         { in = Wp; out = wph; N = CC; bx -= 96; }
    const int K = CC;
    #pragma unroll
    for (int j = 0; j < 4; j++) {
        int k = by * 32 + ty + j * 8;
        ts[ty + j * 8][tx] = in[(size_t)k * N + bx * 32 + tx];
    }
    __syncthreads();
    #pragma unroll
    for (int j = 0; j < 4; j++) {
        int nrow = bx * 32 + ty + j * 8;
        out[(size_t)nrow * K + by * 32 + tx] = __float2half(ts[tx][ty + j * 8]);
    }
}

// ---------------------------------------------------------------------------
// Tensor-core GEMM (large tile), fp16: C = Ah @ Bh^T + bias
// CTA 128x256, 8 warps of 64x64, k128 chunks, 2-stage cp.async, 1 CTA/SM.
// Bias staged in smem. Used for both QKV and proj.
// ---------------------------------------------------------------------------
#define STG_BYTES 98304
#define GSMEM (2 * STG_BYTES + 2048)

template<bool HALF_OUT>
__global__ __launch_bounds__(256, 1) void gemm_mma(
    const __half* __restrict__ Ah, const __half* __restrict__ Bh,
    const float* __restrict__ bias, float* __restrict__ Cf,
    __half* __restrict__ Ch, int Ncols, int K)
{
    extern __shared__ char dsm[];
    const uint32_t sb = (smem_u32(dsm) + 1023u) & ~1023u;
    float* bias_s = (float*)(dsm + ((sb - smem_u32(dsm)) + 2 * STG_BYTES));

    const int tid = threadIdx.x;
    const int lid = tid & 31;
    const int wid = tid >> 5;
    const int wm = (wid >> 2) * 64;
    const int wn = (wid & 3) * 64;
    const int bm = blockIdx.y * 128;
    const int bn = blockIdx.x * 256;

    bias_s[tid] = bias[bn + tid];

    float c[4][8][4];
    #pragma unroll
    for (int mt = 0; mt < 4; mt++)
        #pragma unroll
        for (int nt = 0; nt < 8; nt++)
            #pragma unroll
            for (int e = 0; e < 4; e++) c[mt][nt][e] = 0.f;

    auto load_chunk = [&](int ch, int stg) {
        const int k0 = ch << 7;
        const uint32_t base = sb + (uint32_t)(stg * STG_BYTES);
        #pragma unroll
        for (int j = 0; j < 8; j++) {          // A
            int idx = tid + j * 256;
            int row = idx >> 4;
            int c16f = idx & 15;
            int sub = c16f >> 3, c16 = c16f & 7;
            cp_async16(base + (uint32_t)(sub << 14) + SW(row * 128 + c16 * 16),
                       Ah + (size_t)(bm + row) * K + k0 + sub * 64 + c16 * 8);
        }
        #pragma unroll
        for (int j = 0; j < 16; j++) {         // B
            int idx = tid + j * 256;
            int row = idx >> 4;
            int c16f = idx & 15;
            int sub = c16f >> 3, c16 = c16f & 7;
            cp_async16(base + 32768u + (uint32_t)(sub << 15) + SW(row * 128 + c16 * 16),
                       Bh + (size_t)(bn + row) * K + k0 + sub * 64 + c16 * 8);
        }
    };

    auto compute = [&](int stg) {
        const uint32_t tb = sb + (uint32_t)(stg * STG_BYTES);
        #pragma unroll
        for (int ks = 0; ks < 8; ks++) {
            const int sub = ks >> 2, ksl = ks & 3;
            const uint32_t abase = tb + (uint32_t)(sub << 14);
            const uint32_t bbase = tb + 32768u + (uint32_t)(sub << 15);
            uint32_t ah[4][4];
            #pragma unroll
            for (int mt = 0; mt < 4; mt++) {
                int row = wm + mt * 16 + (lid & 15);
                ldsm_x4(abase + SW(row * 128 + ksl * 32 + ((lid >> 4) << 4)),
                        ah[mt][0], ah[mt][1], ah[mt][2], ah[mt][3]);
            }
            #pragma unroll
            for (int ntp = 0; ntp < 4; ntp++) {
                int rowb = wn + ntp * 16 + ((lid >> 4) << 3) + (lid & 7);
                uint32_t offb = SW(rowb * 128 + ksl * 32 + (((lid >> 3) & 1) << 4));
                uint32_t bh[4];
                ldsm_x4(bbase + offb, bh[0], bh[1], bh[2], bh[3]);
                #pragma unroll
                for (int half = 0; half < 2; half++) {
                    int nt = ntp * 2 + half;
                    #pragma unroll
                    for (int mt = 0; mt < 4; mt++)
                        mma_f16(c[mt][nt], ah[mt][0], ah[mt][1], ah[mt][2], ah[mt][3],
                                bh[half * 2], bh[half * 2 + 1]);
                }
            }
        }
    };

    const int nch = K >> 7;                 // 8 chunks for K=1024
    load_chunk(0, 0); CP_COMMIT();

    for (int ch = 0; ch < nch; ch++) {
        CP_WAIT0();
        __syncthreads();
        if (ch + 1 < nch) { load_chunk(ch + 1, (ch + 1) & 1); CP_COMMIT(); }
        compute(ch & 1);
    }

    #pragma unroll
    for (int mt = 0; mt < 4; mt++) {
        #pragma unroll
        for (int nt = 0; nt < 8; nt++) {
            int m0 = bm + wm + mt * 16 + (lid >> 2);
            int nl = wn + nt * 8 + ((lid & 3) << 1);
            int n  = bn + nl;
            float b0 = bias_s[nl], b1 = bias_s[nl + 1];
            float v00 = c[mt][nt][0] + b0, v01 = c[mt][nt][1] + b1;
            float v10 = c[mt][nt][2] + b0, v11 = c[mt][nt][3] + b1;
            if (HALF_OUT) {
                *(half2*)(Ch + (size_t)m0 * Ncols + n) =
                    __floats2half2_rn(v00, v01);
                *(half2*)(Ch + (size_t)(m0 + 8) * Ncols + n) =
                    __floats2half2_rn(v10, v11);
            } else {
                float2 p0 = {v00, v01}, p1 = {v10, v11};
                *(float2*)(Cf + (size_t)m0 * Ncols + n) = p0;
                *(float2*)(Cf + (size_t)(m0 + 8) * Ncols + n) = p1;
            }
        }
    }
}

// ---------------------------------------------------------------------------
// Flash attention (causal), fp16: S = Qh Kh^T; O += P Vh.
// Block = (b, h, q-tile 128). 4 warps of 32 q-rows, 2 CTAs/SM.
// 3-stage KV pipeline (16KB each: Kh 0 | Vh 8K).
// Softmax: P = ex2.approx.f16x2(pack(s*SCL - mn)); row-sums via ones-mma.
// (R12/R14 configuration — measured optimum.)
// ---------------------------------------------------------------------------
#define KVBUF 16384
#define ATT_SMEM (1024 + 3 * KVBUF)
#define ONES_F16X2 0x3C003C00u

__global__ __launch_bounds__(128, 2) void attn_mma(
    const __half* __restrict__ qkvh, __half* __restrict__ yh)
{
    extern __shared__ char asm_[];
    const uint32_t sb = (smem_u32(asm_) + 1023u) & ~1023u;

    const int tid = threadIdx.x;
    const int lid = tid & 31;
    const int w = tid >> 5;
    const int qt = gridDim.x - 1 - blockIdx.x;    // longest first
    const int h = blockIdx.y;
    const int b = blockIdx.z;
    const size_t bT = (size_t)b * TT;
    const int RS = 3 * CC;
    const float SCL = 0.18033688f;                // 0.125 * log2(e)

    // ---- stage Q (128 x 64 fp16 = 16KB) into buffer0, extract fragments
    {
        const __half* qg = qkvh + (bT + qt * 128) * RS + h * DH;
        #pragma unroll
        for (int j = 0; j < 8; j++) {
            int idx = tid + j * 128;
            int row = idx >> 3, c16 = idx & 7;
            cp_async16(sb + SW(row * 128 + c16 * 16),
                       qg + (size_t)row * RS + c16 * 8);
        }
    }
    CP_COMMIT(); CP_WAIT0();
    __syncthreads();
    uint32_t qh[2][4][4];
    #pragma unroll
    for (int mt = 0; mt < 2; mt++)
        #pragma unroll
        for (int ks = 0; ks < 4; ks++) {
            int row = w * 32 + mt * 16 + (lid & 15);
            ldsm_x4(sb + SW(row * 128 + ks * 32 + ((lid >> 4) << 4)),
                    qh[mt][ks][0], qh[mt][ks][1], qh[mt][ks][2], qh[mt][ks][3]);
        }
    __syncthreads();

    auto load_kv = [&](int kt, int buf) {
        const __half* kh_g = qkvh + (bT + kt * 64) * RS + CC + h * DH;
        const __half* vh_g = kh_g + CC;
        const uint32_t base = sb + (uint32_t)(buf * KVBUF);
        #pragma unroll
        for (int j = 0; j < 8; j++) {
            int idx = tid + j * 128;
            int half = idx >> 9;
            int r = idx & 511;
            int row = r >> 3, c16 = r & 7;
            uint32_t sw = SW(row * 128 + c16 * 16);
            const __half* src = (half ? vh_g : kh_g) + (size_t)row * RS + c16 * 8;
            cp_async16(base + (uint32_t)(half << 13) + sw, src);
        }
    };

    float o[2][8][4];
    #pragma unroll
    for (int mt = 0; mt < 2; mt++)
        #pragma unroll
        for (int nt = 0; nt < 8; nt++)
            #pragma unroll
            for (int e = 0; e < 4; e++) o[mt][nt][e] = 0.f;
    float m[2][2], l[2][2];
    #pragma unroll
    for (int mt = 0; mt < 2; mt++) {
        m[mt][0] = -CUDART_INF_F; m[mt][1] = -CUDART_INF_F;
        l[mt][0] = 0.f; l[mt][1] = 0.f;
    }
    const int gr0 = qt * 128 + w * 32;
    const int r0 = (lid >> 2);
    const int cbase = (lid & 3) << 1;

    const int kt_max = 2 * qt + 1;
    load_kv(0, 0); CP_COMMIT();
    if (kt_max >= 1) { load_kv(1, 1); CP_COMMIT(); }

    for (int kt = 0; kt <= kt_max; kt++) {
        const int buf = kt % 3;
        const uint32_t tb = sb + (uint32_t)(buf * KVBUF);
        if (kt + 1 <= kt_max) CP_WAIT1(); else CP_WAIT0();
        __syncthreads();
        if (kt + 2 <= kt_max) { load_kv(kt + 2, (kt + 2) % 3); CP_COMMIT(); }

        if (kt * 64 <= gr0 + 31) {                // tile not fully masked
            // S_raw = Qh Kh^T  (32 x 64 per warp)
            float s[2][8][4];
            #pragma unroll
            for (int mt = 0; mt < 2; mt++)
                #pragma unroll
                for (int nt = 0; nt < 8; nt++)
                    #pragma unroll
                    for (int e = 0; e < 4; e++) s[mt][nt][e] = 0.f;

            #pragma unroll
            for (int ks = 0; ks < 4; ks++) {
                #pragma unroll
                for (int ntp = 0; ntp < 4; ntp++) {
                    int rowb = ntp * 16 + ((lid >> 4) << 3) + (lid & 7);
                    uint32_t offb = SW(rowb * 128 + ks * 32 + (((lid >> 3) & 1) << 4));
                    uint32_t kh[4];
                    ldsm_x4(tb + offb, kh[0], kh[1], kh[2], kh[3]);
                    #pragma unroll
                    for (int half = 0; half < 2; half++) {
                        int nt = ntp * 2 + half;
                        #pragma unroll
                        for (int mt = 0; mt < 2; mt++)
                            mma_f16(s[mt][nt],
                                    qh[mt][ks][0], qh[mt][ks][1],
                                    qh[mt][ks][2], qh[mt][ks][3],
                                    kh[half * 2], kh[half * 2 + 1]);
                    }
                }
            }

            // causal mask on raw scores (diagonal-overlapping tiles only)
            if (kt * 64 + 63 > gr0) {
                #pragma unroll
                for (int mt = 0; mt < 2; mt++) {
                    int gr = gr0 + mt * 16 + r0;
                    #pragma unroll
                    for (int nt = 0; nt < 8; nt++) {
                        int gc = kt * 64 + nt * 8 + cbase;
                        if (gc     > gr)     s[mt][nt][0] = -CUDART_INF_F;
                        if (gc + 1 > gr)     s[mt][nt][1] = -CUDART_INF_F;
                        if (gc     > gr + 8) s[mt][nt][2] = -CUDART_INF_F;
                        if (gc + 1 > gr + 8) s[mt][nt][3] = -CUDART_INF_F;
                    }
                }
            }

            // row max (raw), running max (log2 domain), alpha, o-rescale
            float mn[2][2], al[2][2];
            #pragma unroll
            for (int mt = 0; mt < 2; mt++) {
                float mx0 = -CUDART_INF_F, mx1 = -CUDART_INF_F;
                #pragma unroll
                for (int nt = 0; nt < 8; nt++) {
                    mx0 = fmaxf(mx0, fmaxf(s[mt][nt][0], s[mt][nt][1]));
                    mx1 = fmaxf(mx1, fmaxf(s[mt][nt][2], s[mt][nt][3]));
                }
                mx0 = fmaxf(mx0, __shfl_xor_sync(0xffffffffu, mx0, 1));
                mx0 = fmaxf(mx0, __shfl_xor_sync(0xffffffffu, mx0, 2));
                mx1 = fmaxf(mx1, __shfl_xor_sync(0xffffffffu, mx1, 1));
                mx1 = fmaxf(mx1, __shfl_xor_sync(0xffffffffu, mx1, 2));
                mn[mt][0] = fmaxf(m[mt][0], mx0 * SCL);
                mn[mt][1] = fmaxf(m[mt][1], mx1 * SCL);
                al[mt][0] = exp2f(m[mt][0] - mn[mt][0]);
                al[mt][1] = exp2f(m[mt][1] - mn[mt][1]);
                m[mt][0] = mn[mt][0];  m[mt][1] = mn[mt][1];
                #pragma unroll
                for (int nt = 0; nt < 8; nt++) {
                    o[mt][nt][0] *= al[mt][0]; o[mt][nt][1] *= al[mt][0];
                    o[mt][nt][2] *= al[mt][1]; o[mt][nt][3] *= al[mt][1];
                }
            }

            // PV with inline P = ex2(pack(s*SCL - mn)); row sums via ones-mma
            float ssum[2][4];
            #pragma unroll
            for (int mt = 0; mt < 2; mt++)
                #pragma unroll
                for (int e = 0; e < 4; e++) ssum[mt][e] = 0.f;

            #pragma unroll
            for (int ks = 0; ks < 4; ks++) {
                uint32_t ph[2][4];
                #pragma unroll
                for (int mt = 0; mt < 2; mt++) {
                    const int t0 = ks * 2, t1 = ks * 2 + 1;
                    float n0 = mn[mt][0], n1 = mn[mt][1];
                    ph[mt][0] = ex2_f16x2(pack_f16x2(
                        fmaf(s[mt][t0][0], SCL, -n0), fmaf(s[mt][t0][1], SCL, -n0)));
                    ph[mt][1] = ex2_f16x2(pack_f16x2(
                        fmaf(s[mt][t0][2], SCL, -n1), fmaf(s[mt][t0][3], SCL, -n1)));
                    ph[mt][2] = ex2_f16x2(pack_f16x2(
                        fmaf(s[mt][t1][0], SCL, -n0), fmaf(s[mt][t1][1], SCL, -n0)));
                    ph[mt][3] = ex2_f16x2(pack_f16x2(
                        fmaf(s[mt][t1][2], SCL, -n1), fmaf(s[mt][t1][3], SCL, -n1)));
                    mma_f16(ssum[mt], ph[mt][0], ph[mt][1], ph[mt][2], ph[mt][3],
                            ONES_F16X2, ONES_F16X2);
                }
                int rowv = ks * 16 + (lid & 15);
                #pragma unroll
                for (int nt2 = 0; nt2 < 4; nt2++) {
                    uint32_t offv = SW(rowv * 128 + nt2 * 32 + ((lid >> 4) << 4));
                    uint32_t vh[4];
                    ldsm_x4t(tb + 8192 + offv, vh[0], vh[1], vh[2], vh[3]);
                    #pragma unroll
                    for (int mt = 0; mt < 2; mt++) {
                        mma_f16(o[mt][nt2 * 2],     ph[mt][0], ph[mt][1],
                                ph[mt][2], ph[mt][3], vh[0], vh[1]);
                        mma_f16(o[mt][nt2 * 2 + 1], ph[mt][0], ph[mt][1],
                                ph[mt][2], ph[mt][3], vh[2], vh[3]);
                    }
                }
            }

            #pragma unroll
            for (int mt = 0; mt < 2; mt++) {
                l[mt][0] = l[mt][0] * al[mt][0] + ssum[mt][0];
                l[mt][1] = l[mt][1] * al[mt][1] + ssum[mt][2];
            }
        }
        __syncthreads();
    }

    // Epilogue: normalize, fp16 out
    #pragma unroll
    for (int mt = 0; mt < 2; mt++) {
        float i0 = 1.f / l[mt][0], i1 = 1.f / l[mt][1];
        size_t row0 = (bT + (size_t)(qt * 128 + w * 32 + mt * 16 + r0)) * CC + h * DH;
        size_t row1 = row0 + (size_t)8 * CC;
        #pragma unroll
        for (int nt = 0; nt < 8; nt++) {
            int n = nt * 8 + cbase;
            *(half2*)(yh + row0 + n) =
                __floats2half2_rn(o[mt][nt][0] * i0, o[mt][nt][1] * i0);
            *(half2*)(yh + row1 + n) =
                __floats2half2_rn(o[mt][nt][2] * i1, o[mt][nt][3] * i1);
        }
    }
}

// ---------------------------------------------------------------------------
extern "C" void kernel_launch(void* const* d_in, const int* in_sizes, int n_in,
                              void* d_out, int out_size)
{
    const float* x      = (const float*)d_in[0];
    const float* W_attn = (const float*)d_in[1];
    const float* b_attn = (const float*)d_in[2];
    const float* W_proj = (const float*)d_in[3];
    const float* b_proj = (const float*)d_in[4];
    float* out = (float*)d_out;

    __half *xh, *qkvh, *yh, *wah, *wph;
    cudaGetSymbolAddress((void**)&xh, g_xh);
    cudaGetSymbolAddress((void**)&qkvh, g_qkvh);
    cudaGetSymbolAddress((void**)&yh, g_yh);
    cudaGetSymbolAddress((void**)&wah, g_wah);
    cudaGetSymbolAddress((void**)&wph, g_wph);

    const int M = BB * TT;       // 4096
    const int N1 = 3 * CC;       // 3072
    const int N2 = CC;           // 1024
    const int K = CC;            // 1024

    cudaFuncSetAttribute(gemm_mma<true>,
                         cudaFuncAttributeMaxDynamicSharedMemorySize, GSMEM);
    cudaFuncSetAttribute(gemm_mma<false>,
                         cudaFuncAttributeMaxDynamicSharedMemorySize, GSMEM);
    cudaFuncSetAttribute(attn_mma,
                         cudaFuncAttributeMaxDynamicSharedMemorySize, ATT_SMEM);

    // Prep (single launch): x -> fp16 and both weights -> transposed fp16
    {
        dim3 grid(160, 32), blk(32, 8);
        cvt_all<<<grid, blk>>>(W_attn, wah, W_proj, wph, x, xh);
    }

    // 1) qkv = x @ W_attn + b_attn  (fp16, large-tile GEMM)
    {
        dim3 grid(N1 / 256, M / 128);
        gemm_mma<true><<<grid, 256, GSMEM>>>(xh, wah, b_attn,
                                             nullptr, qkvh, N1, K);
    }

    // 2) Flash attention -> y (fp16)
    {
        dim3 grid(TT / 128, HH, BB);
        attn_mma<<<grid, 128, ATT_SMEM>>>(qkvh, yh);
    }

    // 3) out = y @ W_proj + b_proj (fp32, large-tile GEMM)
    {
        dim3 grid(N2 / 256, M / 128);
        gemm_mma<false><<<grid, 256, GSMEM>>>(yh, wph, b_proj,
                                              out, nullptr, N2, K);
    }
}